// round 1
// baseline (speedup 1.0000x reference)
#include <cuda_runtime.h>
#include <math.h>

// Problem constants (fixed by setup_inputs)
#define SB   2            // batch
#define SS   2048         // sequence
#define DD   1024         // model dim
#define BSR  4096         // SB*SS rows
#define NEGV (-1e10f)
#define EPSV 1e-5f

// ---------------------------------------------------------------------------
// Scratch (device globals; no allocation allowed in kernel_launch)
// ---------------------------------------------------------------------------
__device__ float g_q[(size_t)BSR * DD];                 // 16 MB
__device__ float g_scores[(size_t)SB * SS * SS];        // 32 MB
__device__ float g_head[(size_t)BSR * DD];              // 16 MB
__device__ float g_h[(size_t)BSR * DD];                 // 16 MB
__device__ float g_f[(size_t)BSR * DD];                 // 16 MB
__device__ float g_wsum[(size_t)DD * DD];               // 4 MB

// ---------------------------------------------------------------------------
// Tiled fp32 GEMM: 128x128 tile, BK=16, 256 threads, 8x8 microtile
// ---------------------------------------------------------------------------
constexpr int BM = 128, BN = 128, BK = 16, TM = 8, TN = 8;

enum { EPI_NONE = 0, EPI_BIAS = 1, EPI_SWISH = 2, EPI_RESID = 3 };

template <int EPI>
__global__ __launch_bounds__(256, 2) void sgemm_nn(
    const float* __restrict__ Abase, const float* __restrict__ Bbase,
    float* __restrict__ Cbase, int M, int N, int K,
    long long sA, long long sB, long long sC,
    const float* __restrict__ Ebase, long long sE, int kLimitCausal)
{
    const float* A = Abase + (long long)blockIdx.z * sA;
    const float* Bm = Bbase + (long long)blockIdx.z * sB;
    float* C = Cbase + (long long)blockIdx.z * sC;
    const float* E = (EPI == EPI_BIAS || EPI == EPI_RESID)
                         ? Ebase + (long long)blockIdx.z * sE : nullptr;

    __shared__ float As[BK][BM];
    __shared__ float Bs[BK][BN];

    const int tid  = threadIdx.x;
    const int row0 = blockIdx.y * BM;
    const int col0 = blockIdx.x * BN;

    // For P@V with causal P: columns k > row are exactly 0, so K-tiles past
    // the diagonal tile contribute nothing.
    const int kEnd = kLimitCausal ? min(K, row0 + BM) : K;

    const int a_r = tid >> 2;            // 0..63
    const int a_c = (tid & 3) << 2;      // 0,4,8,12
    const int b_r = tid >> 5;            // 0..7
    const int b_c = (tid & 31) << 2;     // 0..124
    const int ty  = (tid >> 4) << 3;     // 0..120
    const int tx  = (tid & 15) << 3;     // 0..120

    float acc[TM][TN] = {};

    for (int kk = 0; kk < kEnd; kk += BK) {
#pragma unroll
        for (int i = 0; i < 2; i++) {
            int r = a_r + i * 64;
            float4 v = *reinterpret_cast<const float4*>(
                A + (long long)(row0 + r) * K + kk + a_c);
            As[a_c + 0][r] = v.x; As[a_c + 1][r] = v.y;
            As[a_c + 2][r] = v.z; As[a_c + 3][r] = v.w;
        }
#pragma unroll
        for (int i = 0; i < 2; i++) {
            int r = b_r + i * 8;
            *reinterpret_cast<float4*>(&Bs[r][b_c]) =
                *reinterpret_cast<const float4*>(
                    Bm + (long long)(kk + r) * N + col0 + b_c);
        }
        __syncthreads();
#pragma unroll
        for (int k = 0; k < BK; k++) {
            float ar[TM], br[TN];
#pragma unroll
            for (int i = 0; i < TM; i++) ar[i] = As[k][ty + i];
#pragma unroll
            for (int j = 0; j < TN; j++) br[j] = Bs[k][tx + j];
#pragma unroll
            for (int i = 0; i < TM; i++)
#pragma unroll
                for (int j = 0; j < TN; j++)
                    acc[i][j] += ar[i] * br[j];
        }
        __syncthreads();
    }

#pragma unroll
    for (int i = 0; i < TM; i++) {
        int r = row0 + ty + i;
#pragma unroll
        for (int j = 0; j < TN; j++) {
            int c = col0 + tx + j;
            float v = acc[i][j];
            if (EPI == EPI_BIAS)  v += E[c];
            if (EPI == EPI_RESID) v += E[(long long)r * N + c];
            if (EPI == EPI_SWISH) v = v / (1.0f + expf(-v));
            C[(long long)r * N + c] = v;
        }
    }
}

// ---------------------------------------------------------------------------
// Scores: C = (Q @ Q^T) * scale with causal mask; tiles strictly above the
// diagonal are filled with NEG without computing.
// ---------------------------------------------------------------------------
__global__ __launch_bounds__(256, 2) void sgemm_nt_causal(
    const float* __restrict__ Qg, float* __restrict__ Scg, float scale)
{
    const float* A = Qg + (long long)blockIdx.z * SS * DD;
    float* C = Scg + (long long)blockIdx.z * SS * SS;
    const int tid  = threadIdx.x;
    const int row0 = blockIdx.y * BM;
    const int col0 = blockIdx.x * BN;

    if (col0 >= row0 + BM) {  // fully masked tile
        for (int idx = tid; idx < BM * BN; idx += 256) {
            int i = idx >> 7, j = idx & 127;
            C[(long long)(row0 + i) * SS + col0 + j] = NEGV;
        }
        return;
    }

    __shared__ float As[BK][BM];
    __shared__ float Bs[BK][BN];

    const int a_r = tid >> 2;
    const int a_c = (tid & 3) << 2;
    const int ty  = (tid >> 4) << 3;
    const int tx  = (tid & 15) << 3;

    float acc[TM][TN] = {};

    for (int kk = 0; kk < DD; kk += BK) {
#pragma unroll
        for (int i = 0; i < 2; i++) {
            int r = a_r + i * 64;
            float4 v = *reinterpret_cast<const float4*>(
                A + (long long)(row0 + r) * DD + kk + a_c);
            As[a_c + 0][r] = v.x; As[a_c + 1][r] = v.y;
            As[a_c + 2][r] = v.z; As[a_c + 3][r] = v.w;
            float4 w = *reinterpret_cast<const float4*>(
                A + (long long)(col0 + r) * DD + kk + a_c);
            Bs[a_c + 0][r] = w.x; Bs[a_c + 1][r] = w.y;
            Bs[a_c + 2][r] = w.z; Bs[a_c + 3][r] = w.w;
        }
        __syncthreads();
#pragma unroll
        for (int k = 0; k < BK; k++) {
            float ar[TM], br[TN];
#pragma unroll
            for (int i = 0; i < TM; i++) ar[i] = As[k][ty + i];
#pragma unroll
            for (int j = 0; j < TN; j++) br[j] = Bs[k][tx + j];
#pragma unroll
            for (int i = 0; i < TM; i++)
#pragma unroll
                for (int j = 0; j < TN; j++)
                    acc[i][j] += ar[i] * br[j];
        }
        __syncthreads();
    }

#pragma unroll
    for (int i = 0; i < TM; i++) {
        int r = row0 + ty + i;
#pragma unroll
        for (int j = 0; j < TN; j++) {
            int c = col0 + tx + j;
            C[(long long)r * SS + c] = (c <= r) ? acc[i][j] * scale : NEGV;
        }
    }
}

// ---------------------------------------------------------------------------
// Wsum[d, c] = sum_h out_kernel[h*D + d, c]   (heads identical -> collapse)
// ---------------------------------------------------------------------------
__global__ void wsum_kernel(const float* __restrict__ OK, float* __restrict__ W)
{
    int idx = blockIdx.x * 256 + threadIdx.x;   // 0 .. D*D-1
    float s = 0.f;
#pragma unroll
    for (int h = 0; h < 8; h++) s += OK[(size_t)h * (DD * DD) + idx];
    W[idx] = s;
}

// ---------------------------------------------------------------------------
// Row softmax over scores rows (length SS). One block per row.
// ---------------------------------------------------------------------------
__device__ __forceinline__ float warpMax(float v) {
#pragma unroll
    for (int o = 16; o; o >>= 1) v = fmaxf(v, __shfl_xor_sync(0xffffffffu, v, o));
    return v;
}
__device__ __forceinline__ float warpSum(float v) {
#pragma unroll
    for (int o = 16; o; o >>= 1) v += __shfl_xor_sync(0xffffffffu, v, o);
    return v;
}

__global__ void softmax_rows(float* __restrict__ Scg)
{
    float* row = Scg + (long long)blockIdx.x * SS;
    const int tid  = threadIdx.x;
    const int lane = tid & 31, wid = tid >> 5;
    __shared__ float red[32];

    float m = -3.4e38f;
    for (int j = tid; j < SS; j += 256) m = fmaxf(m, row[j]);
    m = warpMax(m);
    if (lane == 0) red[wid] = m;
    __syncthreads();
    if (tid < 32) {
        float x = (tid < 8) ? red[tid] : -3.4e38f;
        x = warpMax(x);
        if (tid == 0) red[0] = x;
    }
    __syncthreads();
    m = red[0];
    __syncthreads();

    float s = 0.f;
    for (int j = tid; j < SS; j += 256) {
        float e = expf(row[j] - m);
        row[j] = e;
        s += e;
    }
    s = warpSum(s);
    if (lane == 0) red[wid] = s;
    __syncthreads();
    if (tid < 32) {
        float x = (tid < 8) ? red[tid] : 0.f;
        x = warpSum(x);
        if (tid == 0) red[0] = x;
    }
    __syncthreads();
    float inv = 1.0f / red[0];
    for (int j = tid; j < SS; j += 256) row[j] *= inv;
}

// ---------------------------------------------------------------------------
// LayerNorm (no scale/bias), E[x^2]-E[x]^2 variance, in place. One block/row.
// ---------------------------------------------------------------------------
__global__ void layernorm_rows(float* __restrict__ H)
{
    float* row = H + (long long)blockIdx.x * DD;
    const int tid  = threadIdx.x;
    const int lane = tid & 31, wid = tid >> 5;
    __shared__ float r1[32], r2[32];

    float s = 0.f, s2 = 0.f;
    for (int j = tid; j < DD; j += 256) {
        float v = row[j];
        s += v; s2 += v * v;
    }
    s = warpSum(s); s2 = warpSum(s2);
    if (lane == 0) { r1[wid] = s; r2[wid] = s2; }
    __syncthreads();
    if (tid < 32) {
        float a = (tid < 8) ? r1[tid] : 0.f;
        float b = (tid < 8) ? r2[tid] : 0.f;
        a = warpSum(a); b = warpSum(b);
        if (tid == 0) { r1[0] = a; r2[0] = b; }
    }
    __syncthreads();
    float mean = r1[0] * (1.0f / DD);
    float msq  = r2[0] * (1.0f / DD);
    float inv  = rsqrtf(msq - mean * mean + EPSV);
    for (int j = tid; j < DD; j += 256) row[j] = (row[j] - mean) * inv;
}

// ---------------------------------------------------------------------------
// Launch: x, mask(ignored), wi, out_kernel, out_bias, n_heads(ignored)
// ---------------------------------------------------------------------------
extern "C" void kernel_launch(void* const* d_in, const int* in_sizes, int n_in,
                              void* d_out, int out_size)
{
    (void)in_sizes; (void)n_in; (void)out_size;
    const float* x     = (const float*)d_in[0];
    const float* wi    = (const float*)d_in[2];
    const float* okern = (const float*)d_in[3];
    const float* obias = (const float*)d_in[4];
    float* out = (float*)d_out;

    float *q, *sc, *hd, *hh, *ff, *ws;
    cudaGetSymbolAddress((void**)&q,  g_q);
    cudaGetSymbolAddress((void**)&sc, g_scores);
    cudaGetSymbolAddress((void**)&hd, g_head);
    cudaGetSymbolAddress((void**)&hh, g_h);
    cudaGetSymbolAddress((void**)&ff, g_f);
    cudaGetSymbolAddress((void**)&ws, g_wsum);

    const long long sSS = (long long)SS * SS;
    const long long sSD = (long long)SS * DD;

    // Wsum = sum of H out_kernel blocks
    wsum_kernel<<<(DD * DD) / 256, 256>>>(okern, ws);

    // q = x @ wi
    sgemm_nn<EPI_NONE><<<dim3(DD / BN, BSR / BM, 1), 256>>>(
        x, wi, q, BSR, DD, DD, 0, 0, 0, nullptr, 0, 0);

    // scores = causal-masked (q @ q^T) / sqrt(D)
    sgemm_nt_causal<<<dim3(SS / BN, SS / BM, SB), 256>>>(q, sc, 0.03125f);

    // row softmax
    softmax_rows<<<SB * SS, 256>>>(sc);

    // head = q + P @ q   (K-loop truncated at diagonal)
    sgemm_nn<EPI_RESID><<<dim3(DD / BN, SS / BM, SB), 256>>>(
        sc, q, hd, SS, DD, SS, sSS, sSD, sSD, q, sSD, 1);

    // h = head @ Wsum + bias
    sgemm_nn<EPI_BIAS><<<dim3(DD / BN, BSR / BM, 1), 256>>>(
        hd, ws, hh, BSR, DD, DD, 0, 0, 0, obias, 0, 0);

    // layernorm in place
    layernorm_rows<<<BSR, 256>>>(hh);

    // f = swish(h @ wi)
    sgemm_nn<EPI_SWISH><<<dim3(DD / BN, BSR / BM, 1), 256>>>(
        hh, wi, ff, BSR, DD, DD, 0, 0, 0, nullptr, 0, 0);

    // out = f @ wi
    sgemm_nn<EPI_NONE><<<dim3(DD / BN, BSR / BM, 1), 256>>>(
        ff, wi, out, BSR, DD, DD, 0, 0, 0, nullptr, 0, 0);
}

// round 3
// speedup vs baseline: 2.3567x; 2.3567x over previous
#include <cuda_runtime.h>
#include <cuda_bf16.h>
#include <stdint.h>
#include <math.h>

#define SB 2
#define SS 2048
#define DD 1024
#define BSR 4096
#define NEGV (-1e10f)
#define EPSV 1e-5f

// ---------------------------------------------------------------------------
// Scratch carve-out (one big device global; no allocation allowed)
// ---------------------------------------------------------------------------
__device__ __align__(256) unsigned char g_scratch[209715200ULL];  // 200 MB

#define O_QF   0ULL            // q fp32            [4096,1024]
#define O_QH   16777216ULL     // q hi bf16
#define O_QL   25165824ULL
#define O_QTH  33554432ULL     // qT hi bf16        [2][1024][2048]
#define O_QTL  41943040ULL
#define O_XH   50331648ULL     // x split
#define O_XL   58720256ULL
#define O_SC   67108864ULL     // scores fp32       [2][2048][2048]
#define O_PH   100663296ULL    // softmax probs split
#define O_PL   117440512ULL
#define O_HDH  134217728ULL    // head split
#define O_HDL  142606336ULL
#define O_HHF  150994944ULL    // h fp32 (pre-LN)
#define O_HNH  167772160ULL    // h split (post-LN)
#define O_HNL  176160768ULL
#define O_FH   184549376ULL    // swish output split
#define O_FL   192937984ULL
#define O_WTH  201326592ULL    // wi^T split        [1024,1024]
#define O_WTL  203423744ULL
#define O_WSH  205520896ULL    // Wsum^T split
#define O_WSL  207618048ULL

// ---------------------------------------------------------------------------
// Portable sm_80+ primitives: cp.async, ldmatrix, bf16 mma.sync
// ---------------------------------------------------------------------------
__device__ __forceinline__ uint32_t smem_u32(const void* p) {
    uint32_t a;
    asm("{ .reg .u64 t; cvta.to.shared.u64 t, %1; cvt.u32.u64 %0, t; }"
        : "=r"(a) : "l"(p));
    return a;
}
__device__ __forceinline__ void cp16(uint32_t s, const void* g) {
    asm volatile("cp.async.cg.shared.global [%0], [%1], 16;" :: "r"(s), "l"(g));
}
#define CP_COMMIT() asm volatile("cp.async.commit_group;" ::: "memory")
template <int N> __device__ __forceinline__ void cp_wait() {
    asm volatile("cp.async.wait_group %0;" :: "n"(N) : "memory");
}
__device__ __forceinline__ void ldsm4(uint32_t (&r)[4], uint32_t a) {
    asm volatile("ldmatrix.sync.aligned.m8n8.x4.shared.b16 {%0,%1,%2,%3}, [%4];"
                 : "=r"(r[0]), "=r"(r[1]), "=r"(r[2]), "=r"(r[3]) : "r"(a));
}
__device__ __forceinline__ void mma16816(float (&c)[4], const uint32_t (&a)[4],
                                         uint32_t b0, uint32_t b1) {
    asm volatile(
        "mma.sync.aligned.m16n8k16.row.col.f32.bf16.bf16.f32 "
        "{%0,%1,%2,%3}, {%4,%5,%6,%7}, {%8,%9}, {%0,%1,%2,%3};"
        : "+f"(c[0]), "+f"(c[1]), "+f"(c[2]), "+f"(c[3])
        : "r"(a[0]), "r"(a[1]), "r"(a[2]), "r"(a[3]), "r"(b0), "r"(b1));
}

__device__ __forceinline__ void split_f(float v, __nv_bfloat16& h, __nv_bfloat16& l) {
    h = __float2bfloat16(v);
    l = __float2bfloat16(v - __bfloat162float(h));
}

// ---------------------------------------------------------------------------
// GEMM: C[M,N] = A[M,K] @ B[N,K]^T, pre-split bf16 hi/lo, mma.sync HMMA.
// CTA tile 128x128, 8 warps (2m x 4n of 64x32), K-chunk 32, cp.async 2-stage.
// smem rows padded to 40 bf16 (80B) -> conflict-free ldmatrix & cp.async STS.
// ---------------------------------------------------------------------------
enum { EP_Q = 0, EP_SC = 1, EP_HEAD = 2, EP_BIAS = 3, EP_SWISH = 4, EP_OUT = 5 };

#define RPAD 40
#define MATB (128 * RPAD * 2)     // 10240 bytes per matrix tile
#define OFF_AH 0
#define OFF_AL (MATB)
#define OFF_BH (2 * MATB)
#define OFF_BL (3 * MATB)
#define STAGEB (4 * MATB)         // 40960
#define GEMM_SMEM (2 * STAGEB)    // 81920

template <int EPI>
__global__ __launch_bounds__(256, 1) void gemm_bb(
    const __nv_bfloat16* __restrict__ Agh, const __nv_bfloat16* __restrict__ Agl,
    const __nv_bfloat16* __restrict__ Bgh, const __nv_bfloat16* __restrict__ Bgl,
    float* __restrict__ Cf, __nv_bfloat16* __restrict__ Ch,
    __nv_bfloat16* __restrict__ Cl, const float* __restrict__ E,
    int K, int N, long long sA, long long sB, long long sC, long long sE,
    int causal)
{
    extern __shared__ unsigned char smb[];

    const int tid = threadIdx.x;
    const int wid = tid >> 5;
    const int lane = tid & 31;
    const int row0 = blockIdx.y * 128;
    const int col0 = blockIdx.x * 128;
    const int z = blockIdx.z;

    // scores: tile entirely above diagonal -> NEG fill, no compute
    if (EPI == EP_SC && col0 > row0) {
        float* C = Cf + (long long)z * sC;
        float4 v = make_float4(NEGV, NEGV, NEGV, NEGV);
        for (int i = tid; i < 128 * 32; i += 256) {
            int r = i >> 5, c4 = (i & 31) * 4;
            *reinterpret_cast<float4*>(&C[(long long)(row0 + r) * N + col0 + c4]) = v;
        }
        return;
    }

    const __nv_bfloat16* Ah = Agh + (long long)z * sA;
    const __nv_bfloat16* Al = Agl + (long long)z * sA;
    const __nv_bfloat16* Bh = Bgh + (long long)z * sB;
    const __nv_bfloat16* Bl = Bgl + (long long)z * sB;

    const int kEnd = (causal == 2) ? min(K, row0 + 128) : K;
    const int nch = kEnd >> 5;

    const uint32_t sbase = smem_u32(smb);

    // ---- loader mapping: thread -> row tid>>1, two 16B quads (tid&1)*2+{0,1}
    const int ldr = tid >> 1;
    const int ldq = (tid & 1) * 2;
    const size_t aRow = (size_t)(row0 + ldr) * K;
    const size_t bRow = (size_t)(col0 + ldr) * K;
    const uint32_t sRow = (uint32_t)(ldr * (RPAD * 2));  // byte offset of row

    // ---- warp tile ----
    const int m0 = (wid >> 2) * 64;
    const int n0 = (wid & 3) * 32;

    // ldmatrix per-thread byte offsets (relative to stage base, ks=0)
    // A (x4, one m-tile): row = m0 + mt*16 + (lane&15), colgrp = (lane>>4)*8
    uint32_t aoff[4];
#pragma unroll
    for (int mt = 0; mt < 4; mt++)
        aoff[mt] = (uint32_t)((m0 + mt * 16 + (lane & 15)) * (RPAD * 2) +
                              ((lane >> 4) * 8) * 2);
    // B (x4, two n-tiles p*2, p*2+1):
    // row = n0 + p*16 + ((lane>>4)<<3) + (lane&7), colgrp = ((lane>>3)&1)*8
    uint32_t boff[2];
#pragma unroll
    for (int p = 0; p < 2; p++)
        boff[p] = (uint32_t)((n0 + p * 16 + ((lane >> 4) << 3) + (lane & 7)) *
                                 (RPAD * 2) +
                             (((lane >> 3) & 1) * 8) * 2);

    float acc[4][4][4] = {};

    // ---- cp.async issue for chunk c into stage st ----
#define ISSUE(c, st) { \
    const int kk = (c) * 32; \
    const uint32_t sb = sbase + (st) * STAGEB + sRow; \
    _Pragma("unroll") for (int u = 0; u < 2; u++) { \
        const int q = ldq + u; \
        cp16(sb + OFF_AH + q * 16, Ah + aRow + kk + q * 8); \
        cp16(sb + OFF_AL + q * 16, Al + aRow + kk + q * 8); \
        cp16(sb + OFF_BH + q * 16, Bh + bRow + kk + q * 8); \
        cp16(sb + OFF_BL + q * 16, Bl + bRow + kk + q * 8); \
    } }

    ISSUE(0, 0);
    CP_COMMIT();

    for (int c = 0; c < nch; c++) {
        if (c + 1 < nch) {
            ISSUE(c + 1, (c + 1) & 1);
            CP_COMMIT();
            cp_wait<1>();
        } else {
            cp_wait<0>();
        }
        __syncthreads();

        const uint32_t stb = sbase + (c & 1) * STAGEB;
#pragma unroll
        for (int ks = 0; ks < 2; ks++) {
            const uint32_t kso = (uint32_t)(ks * 16 * 2);
            uint32_t ahf[4][4], alf[4][4], bhf[2][4], blf[2][4];
#pragma unroll
            for (int mt = 0; mt < 4; mt++) {
                ldsm4(ahf[mt], stb + OFF_AH + aoff[mt] + kso);
                ldsm4(alf[mt], stb + OFF_AL + aoff[mt] + kso);
            }
#pragma unroll
            for (int p = 0; p < 2; p++) {
                ldsm4(bhf[p], stb + OFF_BH + boff[p] + kso);
                ldsm4(blf[p], stb + OFF_BL + boff[p] + kso);
            }
#pragma unroll
            for (int mt = 0; mt < 4; mt++)
#pragma unroll
                for (int nt = 0; nt < 4; nt++) {
                    const int p = nt >> 1, h = (nt & 1) * 2;
                    mma16816(acc[mt][nt], ahf[mt], bhf[p][h], bhf[p][h + 1]);
                    mma16816(acc[mt][nt], ahf[mt], blf[p][h], blf[p][h + 1]);
                    mma16816(acc[mt][nt], alf[mt], bhf[p][h], bhf[p][h + 1]);
                }
        }
        __syncthreads();
    }
#undef ISSUE

    // ------------------- epilogue -------------------
    float* Cfz = (EPI == EP_Q || EPI == EP_SC || EPI == EP_BIAS || EPI == EP_OUT)
                     ? Cf + (long long)z * sC : nullptr;
    __nv_bfloat16* Chz = (EPI == EP_Q || EPI == EP_HEAD || EPI == EP_SWISH)
                             ? Ch + (long long)z * sC : nullptr;
    __nv_bfloat16* Clz = (EPI == EP_Q || EPI == EP_HEAD || EPI == EP_SWISH)
                             ? Cl + (long long)z * sC : nullptr;
    const float* Eq = (EPI == EP_HEAD) ? E + (long long)z * sE : nullptr;
    const bool diag = (EPI == EP_SC) && (col0 == row0);

#pragma unroll
    for (int mt = 0; mt < 4; mt++) {
#pragma unroll
        for (int nt = 0; nt < 4; nt++) {
#pragma unroll
            for (int half = 0; half < 2; half++) {
                const int r = row0 + m0 + mt * 16 + (lane >> 2) + half * 8;
                const int cc = col0 + n0 + nt * 8 + (lane & 3) * 2;
                float v0 = acc[mt][nt][half * 2];
                float v1 = acc[mt][nt][half * 2 + 1];

                if (EPI == EP_SC) {
                    v0 *= 0.03125f; v1 *= 0.03125f;
                    if (diag) {
                        if (cc > r) v0 = NEGV;
                        if (cc + 1 > r) v1 = NEGV;
                    }
                    *reinterpret_cast<float2*>(&Cfz[(long long)r * N + cc]) =
                        make_float2(v0, v1);
                } else if (EPI == EP_BIAS) {
                    float2 bb = *reinterpret_cast<const float2*>(&E[cc]);
                    *reinterpret_cast<float2*>(&Cfz[(long long)r * N + cc]) =
                        make_float2(v0 + bb.x, v1 + bb.y);
                } else if (EPI == EP_OUT) {
                    *reinterpret_cast<float2*>(&Cfz[(long long)r * N + cc]) =
                        make_float2(v0, v1);
                } else {
                    if (EPI == EP_HEAD) {
                        float2 ee = *reinterpret_cast<const float2*>(
                            &Eq[(long long)r * N + cc]);
                        v0 += ee.x; v1 += ee.y;
                    }
                    if (EPI == EP_SWISH) {
                        v0 = v0 / (1.0f + expf(-v0));
                        v1 = v1 / (1.0f + expf(-v1));
                    }
                    if (EPI == EP_Q)
                        *reinterpret_cast<float2*>(&Cfz[(long long)r * N + cc]) =
                            make_float2(v0, v1);
                    __nv_bfloat16 h0, h1, l0, l1;
                    split_f(v0, h0, l0);
                    split_f(v1, h1, l1);
                    *reinterpret_cast<__nv_bfloat162*>(&Chz[(long long)r * N + cc]) =
                        __halves2bfloat162(h0, h1);
                    *reinterpret_cast<__nv_bfloat162*>(&Clz[(long long)r * N + cc]) =
                        __halves2bfloat162(l0, l1);
                }
            }
        }
    }
}

// ---------------------------------------------------------------------------
// Transpose + split: dst[c][r] = split(src[r][c]); optional sum over 8 heads
// ---------------------------------------------------------------------------
template <bool SUMH>
__global__ void tsplit(const float* __restrict__ S, __nv_bfloat16* __restrict__ Dh,
                       __nv_bfloat16* __restrict__ Dl, int R, int C,
                       long long sS, long long sD)
{
    __shared__ float t[32][33];
    const int tx = threadIdx.x, ty = threadIdx.y;
    const int c0 = blockIdx.x * 32, r0 = blockIdx.y * 32, z = blockIdx.z;
    const float* Sz = S + (long long)z * sS;
#pragma unroll
    for (int i = 0; i < 4; i++) {
        int r = r0 + ty + i * 8;
        float v;
        if (SUMH) {
            v = 0.f;
#pragma unroll
            for (int h = 0; h < 8; h++)
                v += S[(size_t)(h * 1024 + r) * C + c0 + tx];
        } else {
            v = Sz[(size_t)r * C + c0 + tx];
        }
        t[ty + i * 8][tx] = v;
    }
    __syncthreads();
#pragma unroll
    for (int i = 0; i < 4; i++) {
        int orow = c0 + ty + i * 8;
        float v = t[tx][ty + i * 8];
        __nv_bfloat16 h, l;
        split_f(v, h, l);
        Dh[(long long)z * sD + (size_t)orow * R + r0 + tx] = h;
        Dl[(long long)z * sD + (size_t)orow * R + r0 + tx] = l;
    }
}

// ---------------------------------------------------------------------------
// Elementwise split
// ---------------------------------------------------------------------------
__global__ void split_ew(const float* __restrict__ X, __nv_bfloat16* __restrict__ H,
                         __nv_bfloat16* __restrict__ L)
{
    size_t i = ((size_t)blockIdx.x * 256 + threadIdx.x);
    float4 v = reinterpret_cast<const float4*>(X)[i];
    __nv_bfloat16 h0, h1, h2, h3, l0, l1, l2, l3;
    split_f(v.x, h0, l0); split_f(v.y, h1, l1);
    split_f(v.z, h2, l2); split_f(v.w, h3, l3);
    reinterpret_cast<__nv_bfloat162*>(H)[i * 2]     = __halves2bfloat162(h0, h1);
    reinterpret_cast<__nv_bfloat162*>(H)[i * 2 + 1] = __halves2bfloat162(h2, h3);
    reinterpret_cast<__nv_bfloat162*>(L)[i * 2]     = __halves2bfloat162(l0, l1);
    reinterpret_cast<__nv_bfloat162*>(L)[i * 2 + 1] = __halves2bfloat162(l2, l3);
}

// ---------------------------------------------------------------------------
// Reductions
// ---------------------------------------------------------------------------
__device__ __forceinline__ float warpMax(float v) {
#pragma unroll
    for (int o = 16; o; o >>= 1) v = fmaxf(v, __shfl_xor_sync(0xffffffffu, v, o));
    return v;
}
__device__ __forceinline__ float warpSum(float v) {
#pragma unroll
    for (int o = 16; o; o >>= 1) v += __shfl_xor_sync(0xffffffffu, v, o);
    return v;
}

// Softmax over scores rows; writes split probs. One block per row (2048 cols).
__global__ __launch_bounds__(256) void softmax_split(
    const float* __restrict__ Sc, __nv_bfloat16* __restrict__ Ph,
    __nv_bfloat16* __restrict__ Pl)
{
    const float* row = Sc + (long long)blockIdx.x * SS;
    __nv_bfloat16* oh = Ph + (long long)blockIdx.x * SS;
    __nv_bfloat16* ol = Pl + (long long)blockIdx.x * SS;
    const int tid = threadIdx.x, lane = tid & 31, w = tid >> 5;
    __shared__ float red[32];

    float4 v0 = reinterpret_cast<const float4*>(row)[tid];
    float4 v1 = reinterpret_cast<const float4*>(row)[tid + 256];
    float m = fmaxf(fmaxf(fmaxf(v0.x, v0.y), fmaxf(v0.z, v0.w)),
                    fmaxf(fmaxf(v1.x, v1.y), fmaxf(v1.z, v1.w)));
    m = warpMax(m);
    if (lane == 0) red[w] = m;
    __syncthreads();
    if (tid < 32) { float x = (tid < 8) ? red[tid] : -3.4e38f; x = warpMax(x);
                    if (tid == 0) red[0] = x; }
    __syncthreads();
    m = red[0];
    __syncthreads();

    float e0x = expf(v0.x - m), e0y = expf(v0.y - m),
          e0z = expf(v0.z - m), e0w = expf(v0.w - m);
    float e1x = expf(v1.x - m), e1y = expf(v1.y - m),
          e1z = expf(v1.z - m), e1w = expf(v1.w - m);
    float s = e0x + e0y + e0z + e0w + e1x + e1y + e1z + e1w;
    s = warpSum(s);
    if (lane == 0) red[w] = s;
    __syncthreads();
    if (tid < 32) { float x = (tid < 8) ? red[tid] : 0.f; x = warpSum(x);
                    if (tid == 0) red[0] = x; }
    __syncthreads();
    const float inv = 1.0f / red[0];

    float p[8] = {e0x * inv, e0y * inv, e0z * inv, e0w * inv,
                  e1x * inv, e1y * inv, e1z * inv, e1w * inv};
    __nv_bfloat16 h[8], l[8];
#pragma unroll
    for (int u = 0; u < 8; u++) split_f(p[u], h[u], l[u]);
    __nv_bfloat162* phh = reinterpret_cast<__nv_bfloat162*>(oh);
    __nv_bfloat162* pll = reinterpret_cast<__nv_bfloat162*>(ol);
    phh[tid * 2]             = __halves2bfloat162(h[0], h[1]);
    phh[tid * 2 + 1]         = __halves2bfloat162(h[2], h[3]);
    phh[(tid + 256) * 2]     = __halves2bfloat162(h[4], h[5]);
    phh[(tid + 256) * 2 + 1] = __halves2bfloat162(h[6], h[7]);
    pll[tid * 2]             = __halves2bfloat162(l[0], l[1]);
    pll[tid * 2 + 1]         = __halves2bfloat162(l[2], l[3]);
    pll[(tid + 256) * 2]     = __halves2bfloat162(l[4], l[5]);
    pll[(tid + 256) * 2 + 1] = __halves2bfloat162(l[6], l[7]);
}

// LayerNorm -> split. One block per row (1024 cols).
__global__ __launch_bounds__(256) void ln_split(
    const float* __restrict__ Hf, __nv_bfloat16* __restrict__ Oh,
    __nv_bfloat16* __restrict__ Ol)
{
    const float* row = Hf + (long long)blockIdx.x * DD;
    __nv_bfloat16* oh = Oh + (long long)blockIdx.x * DD;
    __nv_bfloat16* ol = Ol + (long long)blockIdx.x * DD;
    const int tid = threadIdx.x, lane = tid & 31, w = tid >> 5;
    __shared__ float r1[32], r2[32];

    float4 v = reinterpret_cast<const float4*>(row)[tid];
    float s = v.x + v.y + v.z + v.w;
    float s2 = v.x * v.x + v.y * v.y + v.z * v.z + v.w * v.w;
    s = warpSum(s); s2 = warpSum(s2);
    if (lane == 0) { r1[w] = s; r2[w] = s2; }
    __syncthreads();
    if (tid < 32) {
        float a = (tid < 8) ? r1[tid] : 0.f;
        float b = (tid < 8) ? r2[tid] : 0.f;
        a = warpSum(a); b = warpSum(b);
        if (tid == 0) { r1[0] = a; r2[0] = b; }
    }
    __syncthreads();
    const float mean = r1[0] * (1.0f / DD);
    const float msq = r2[0] * (1.0f / DD);
    const float inv = rsqrtf(msq - mean * mean + EPSV);

    float y[4] = {(v.x - mean) * inv, (v.y - mean) * inv,
                  (v.z - mean) * inv, (v.w - mean) * inv};
    __nv_bfloat16 h[4], l[4];
#pragma unroll
    for (int u = 0; u < 4; u++) split_f(y[u], h[u], l[u]);
    reinterpret_cast<__nv_bfloat162*>(oh)[tid * 2]     = __halves2bfloat162(h[0], h[1]);
    reinterpret_cast<__nv_bfloat162*>(oh)[tid * 2 + 1] = __halves2bfloat162(h[2], h[3]);
    reinterpret_cast<__nv_bfloat162*>(ol)[tid * 2]     = __halves2bfloat162(l[0], l[1]);
    reinterpret_cast<__nv_bfloat162*>(ol)[tid * 2 + 1] = __halves2bfloat162(l[2], l[3]);
}

// ---------------------------------------------------------------------------
// Launch
// ---------------------------------------------------------------------------
extern "C" void kernel_launch(void* const* d_in, const int* in_sizes, int n_in,
                              void* d_out, int out_size)
{
    (void)in_sizes; (void)n_in; (void)out_size;
    const float* x     = (const float*)d_in[0];
    const float* wi    = (const float*)d_in[2];
    const float* okern = (const float*)d_in[3];
    const float* obias = (const float*)d_in[4];
    float* out = (float*)d_out;

    unsigned char* base;
    cudaGetSymbolAddress((void**)&base, g_scratch);
    float* qf  = (float*)(base + O_QF);
    float* sc  = (float*)(base + O_SC);
    float* hhf = (float*)(base + O_HHF);
    __nv_bfloat16* qh  = (__nv_bfloat16*)(base + O_QH);
    __nv_bfloat16* ql  = (__nv_bfloat16*)(base + O_QL);
    __nv_bfloat16* qTh = (__nv_bfloat16*)(base + O_QTH);
    __nv_bfloat16* qTl = (__nv_bfloat16*)(base + O_QTL);
    __nv_bfloat16* xh  = (__nv_bfloat16*)(base + O_XH);
    __nv_bfloat16* xl  = (__nv_bfloat16*)(base + O_XL);
    __nv_bfloat16* Pph = (__nv_bfloat16*)(base + O_PH);
    __nv_bfloat16* Ppl = (__nv_bfloat16*)(base + O_PL);
    __nv_bfloat16* hdh = (__nv_bfloat16*)(base + O_HDH);
    __nv_bfloat16* hdl = (__nv_bfloat16*)(base + O_HDL);
    __nv_bfloat16* hnh = (__nv_bfloat16*)(base + O_HNH);
    __nv_bfloat16* hnl = (__nv_bfloat16*)(base + O_HNL);
    __nv_bfloat16* fh  = (__nv_bfloat16*)(base + O_FH);
    __nv_bfloat16* fl  = (__nv_bfloat16*)(base + O_FL);
    __nv_bfloat16* wTh = (__nv_bfloat16*)(base + O_WTH);
    __nv_bfloat16* wTl = (__nv_bfloat16*)(base + O_WTL);
    __nv_bfloat16* wsh = (__nv_bfloat16*)(base + O_WSH);
    __nv_bfloat16* wsl = (__nv_bfloat16*)(base + O_WSL);

    cudaFuncSetAttribute(gemm_bb<EP_Q>,     cudaFuncAttributeMaxDynamicSharedMemorySize, GEMM_SMEM);
    cudaFuncSetAttribute(gemm_bb<EP_SC>,    cudaFuncAttributeMaxDynamicSharedMemorySize, GEMM_SMEM);
    cudaFuncSetAttribute(gemm_bb<EP_HEAD>,  cudaFuncAttributeMaxDynamicSharedMemorySize, GEMM_SMEM);
    cudaFuncSetAttribute(gemm_bb<EP_BIAS>,  cudaFuncAttributeMaxDynamicSharedMemorySize, GEMM_SMEM);
    cudaFuncSetAttribute(gemm_bb<EP_SWISH>, cudaFuncAttributeMaxDynamicSharedMemorySize, GEMM_SMEM);
    cudaFuncSetAttribute(gemm_bb<EP_OUT>,   cudaFuncAttributeMaxDynamicSharedMemorySize, GEMM_SMEM);

    const long long sSD = (long long)SS * DD;   // 2,097,152
    const long long sSS = (long long)SS * SS;   // 4,194,304
    dim3 tb(32, 8);

    // wi^T split, Wsum^T split, x split
    tsplit<false><<<dim3(32, 32, 1), tb>>>(wi, wTh, wTl, DD, DD, 0, 0);
    tsplit<true><<<dim3(32, 32, 1), tb>>>(okern, wsh, wsl, DD, DD, 0, 0);
    split_ew<<<(BSR * DD) / 1024, 256>>>(x, xh, xl);

    // q = x @ wi  (fp32 + split)
    gemm_bb<EP_Q><<<dim3(8, 32, 1), 256, GEMM_SMEM>>>(
        xh, xl, wTh, wTl, qf, qh, ql, nullptr, DD, DD, 0, 0, 0, 0, 0);

    // q^T split per batch
    tsplit<false><<<dim3(32, 64, 2), tb>>>(qf, qTh, qTl, SS, DD, sSD, sSD);

    // scores = causal((q @ q^T)/32)  fp32
    gemm_bb<EP_SC><<<dim3(16, 16, 2), 256, GEMM_SMEM>>>(
        qh, ql, qh, ql, sc, nullptr, nullptr, nullptr,
        DD, SS, sSD, sSD, sSS, 0, 1);

    // softmax -> split probs
    softmax_split<<<SB * SS, 256>>>(sc, Pph, Ppl);

    // head = q + P @ q  (split out; K truncated at diagonal)
    gemm_bb<EP_HEAD><<<dim3(8, 16, 2), 256, GEMM_SMEM>>>(
        Pph, Ppl, qTh, qTl, nullptr, hdh, hdl, qf,
        SS, DD, sSS, sSD, sSD, sSD, 2);

    // h = head @ Wsum + bias  fp32
    gemm_bb<EP_BIAS><<<dim3(8, 32, 1), 256, GEMM_SMEM>>>(
        hdh, hdl, wsh, wsl, hhf, nullptr, nullptr, obias,
        DD, DD, 0, 0, 0, 0, 0);

    // layernorm -> split
    ln_split<<<BSR, 256>>>(hhf, hnh, hnl);

    // f = swish(h @ wi)  (split out)
    gemm_bb<EP_SWISH><<<dim3(8, 32, 1), 256, GEMM_SMEM>>>(
        hnh, hnl, wTh, wTl, nullptr, fh, fl, nullptr,
        DD, DD, 0, 0, 0, 0, 0);

    // out = f @ wi  fp32
    gemm_bb<EP_OUT><<<dim3(8, 32, 1), 256, GEMM_SMEM>>>(
        fh, fl, wTh, wTl, out, nullptr, nullptr, nullptr,
        DD, DD, 0, 0, 0, 0, 0);
}

// round 4
// speedup vs baseline: 2.4353x; 1.0334x over previous
#include <cuda_runtime.h>
#include <cuda_bf16.h>
#include <stdint.h>
#include <math.h>

#define SB 2
#define SS 2048
#define DD 1024
#define BSR 4096
#define NEGV (-1e10f)
#define EPSV 1e-5f

// ---------------------------------------------------------------------------
// Scratch carve-out (one big device global; no allocation allowed)
// ---------------------------------------------------------------------------
__device__ __align__(256) unsigned char g_scratch[209715200ULL];  // 200 MB

#define O_QF   0ULL            // q fp32            [4096,1024]
#define O_QH   16777216ULL     // q hi bf16
#define O_QL   25165824ULL
#define O_QTH  33554432ULL     // qT hi bf16        [2][1024][2048]
#define O_QTL  41943040ULL
#define O_XH   50331648ULL     // x split
#define O_XL   58720256ULL
#define O_SC   67108864ULL     // scores fp32       [2][2048][2048]
#define O_PH   100663296ULL    // softmax probs split
#define O_PL   117440512ULL
#define O_HDH  134217728ULL    // head split
#define O_HDL  142606336ULL
#define O_HHF  150994944ULL    // h fp32 (pre-LN)
#define O_HNH  167772160ULL    // h split (post-LN)
#define O_HNL  176160768ULL
#define O_FH   184549376ULL    // swish output split
#define O_FL   192937984ULL
#define O_WTH  201326592ULL    // wi^T split        [1024,1024]
#define O_WTL  203423744ULL
#define O_WSH  205520896ULL    // Wsum^T split
#define O_WSL  207618048ULL

// ---------------------------------------------------------------------------
// Portable sm_80+ primitives: cp.async, ldmatrix, bf16 mma.sync
// ---------------------------------------------------------------------------
__device__ __forceinline__ uint32_t smem_u32(const void* p) {
    uint32_t a;
    asm("{ .reg .u64 t; cvta.to.shared.u64 t, %1; cvt.u32.u64 %0, t; }"
        : "=r"(a) : "l"(p));
    return a;
}
__device__ __forceinline__ void cp16(uint32_t s, const void* g) {
    asm volatile("cp.async.cg.shared.global [%0], [%1], 16;" :: "r"(s), "l"(g));
}
#define CP_COMMIT() asm volatile("cp.async.commit_group;" ::: "memory")
template <int N> __device__ __forceinline__ void cp_wait() {
    asm volatile("cp.async.wait_group %0;" :: "n"(N) : "memory");
}
__device__ __forceinline__ void ldsm4(uint32_t (&r)[4], uint32_t a) {
    asm volatile("ldmatrix.sync.aligned.m8n8.x4.shared.b16 {%0,%1,%2,%3}, [%4];"
                 : "=r"(r[0]), "=r"(r[1]), "=r"(r[2]), "=r"(r[3]) : "r"(a));
}
__device__ __forceinline__ void mma16816(float (&c)[4], const uint32_t (&a)[4],
                                         uint32_t b0, uint32_t b1) {
    asm volatile(
        "mma.sync.aligned.m16n8k16.row.col.f32.bf16.bf16.f32 "
        "{%0,%1,%2,%3}, {%4,%5,%6,%7}, {%8,%9}, {%0,%1,%2,%3};"
        : "+f"(c[0]), "+f"(c[1]), "+f"(c[2]), "+f"(c[3])
        : "r"(a[0]), "r"(a[1]), "r"(a[2]), "r"(a[3]), "r"(b0), "r"(b1));
}

__device__ __forceinline__ void split_f(float v, __nv_bfloat16& h, __nv_bfloat16& l) {
    h = __float2bfloat16(v);
    l = __float2bfloat16(v - __bfloat162float(h));
}

// ---------------------------------------------------------------------------
// GEMM: C[M,N] = A[M,K] @ B[N,K]^T, pre-split bf16 hi/lo, mma.sync HMMA.
// CTA tile 128x128, 8 warps (2m x 4n of 64x32), K-chunk 32, cp.async 4-stage,
// register-level fragment double buffering inside the chunk.
// ---------------------------------------------------------------------------
enum { EP_Q = 0, EP_SC = 1, EP_HEAD = 2, EP_BIAS = 3, EP_SWISH = 4, EP_OUT = 5 };

#define RPAD 40
#define MATB (128 * RPAD * 2)     // 10240 bytes per matrix tile
#define OFF_AH 0
#define OFF_AL (MATB)
#define OFF_BH (2 * MATB)
#define OFF_BL (3 * MATB)
#define STAGEB (4 * MATB)         // 40960
#define NSTAGE 4
#define GEMM_SMEM (NSTAGE * STAGEB)  // 163840

template <int EPI>
__global__ __launch_bounds__(256, 1) void gemm_bb(
    const __nv_bfloat16* __restrict__ Agh, const __nv_bfloat16* __restrict__ Agl,
    const __nv_bfloat16* __restrict__ Bgh, const __nv_bfloat16* __restrict__ Bgl,
    float* __restrict__ Cf, __nv_bfloat16* __restrict__ Ch,
    __nv_bfloat16* __restrict__ Cl, const float* __restrict__ E,
    int K, int N, long long sA, long long sB, long long sC, long long sE,
    int causal)
{
    extern __shared__ unsigned char smb[];

    const int tid = threadIdx.x;
    const int wid = tid >> 5;
    const int lane = tid & 31;
    const int row0 = blockIdx.y * 128;
    const int col0 = blockIdx.x * 128;
    const int z = blockIdx.z;

    // scores: tile entirely above diagonal -> NEG fill, no compute
    if (EPI == EP_SC && col0 > row0) {
        float* C = Cf + (long long)z * sC;
        float4 v = make_float4(NEGV, NEGV, NEGV, NEGV);
        for (int i = tid; i < 128 * 32; i += 256) {
            int r = i >> 5, c4 = (i & 31) * 4;
            *reinterpret_cast<float4*>(&C[(long long)(row0 + r) * N + col0 + c4]) = v;
        }
        return;
    }

    const __nv_bfloat16* Ah = Agh + (long long)z * sA;
    const __nv_bfloat16* Al = Agl + (long long)z * sA;
    const __nv_bfloat16* Bh = Bgh + (long long)z * sB;
    const __nv_bfloat16* Bl = Bgl + (long long)z * sB;

    const int kEnd = (causal == 2) ? min(K, row0 + 128) : K;
    const int nch = kEnd >> 5;

    const uint32_t sbase = smem_u32(smb);

    // ---- loader mapping: thread -> row tid>>1, two 16B quads (tid&1)*2+{0,1}
    const int ldr = tid >> 1;
    const int ldq = (tid & 1) * 2;
    const size_t aRow = (size_t)(row0 + ldr) * K;
    const size_t bRow = (size_t)(col0 + ldr) * K;
    const uint32_t sRow = (uint32_t)(ldr * (RPAD * 2));  // byte offset of row

    // ---- warp tile ----
    const int m0 = (wid >> 2) * 64;
    const int n0 = (wid & 3) * 32;

    // ldmatrix per-thread byte offsets (relative to stage base, ks=0)
    uint32_t aoff[4];
#pragma unroll
    for (int mt = 0; mt < 4; mt++)
        aoff[mt] = (uint32_t)((m0 + mt * 16 + (lane & 15)) * (RPAD * 2) +
                              ((lane >> 4) * 8) * 2);
    uint32_t boff[2];
#pragma unroll
    for (int p = 0; p < 2; p++)
        boff[p] = (uint32_t)((n0 + p * 16 + ((lane >> 4) << 3) + (lane & 7)) *
                                 (RPAD * 2) +
                             (((lane >> 3) & 1) * 8) * 2);

    float acc[4][4][4] = {};

#define ISSUE(c, st) { \
    const int kk = (c) * 32; \
    const uint32_t sb = sbase + (st) * STAGEB + sRow; \
    _Pragma("unroll") for (int u = 0; u < 2; u++) { \
        const int q = ldq + u; \
        cp16(sb + OFF_AH + q * 16, Ah + aRow + kk + q * 8); \
        cp16(sb + OFF_AL + q * 16, Al + aRow + kk + q * 8); \
        cp16(sb + OFF_BH + q * 16, Bh + bRow + kk + q * 8); \
        cp16(sb + OFF_BL + q * 16, Bl + bRow + kk + q * 8); \
    } }

    // Prologue: fill 3 stages
#pragma unroll
    for (int pc = 0; pc < NSTAGE - 1; pc++) {
        if (pc < nch) ISSUE(pc, pc);
        CP_COMMIT();
    }

    uint32_t ahf[2][4][4], alf[2][4][4], bhf[2][2][4], blf[2][2][4];

#define LOADFRAG(buf, stb, kso) { \
    _Pragma("unroll") for (int mt = 0; mt < 4; mt++) { \
        ldsm4(ahf[buf][mt], (stb) + OFF_AH + aoff[mt] + (kso)); \
        ldsm4(alf[buf][mt], (stb) + OFF_AL + aoff[mt] + (kso)); \
    } \
    _Pragma("unroll") for (int p = 0; p < 2; p++) { \
        ldsm4(bhf[buf][p], (stb) + OFF_BH + boff[p] + (kso)); \
        ldsm4(blf[buf][p], (stb) + OFF_BL + boff[p] + (kso)); \
    } }

#define DOMMA(buf) { \
    _Pragma("unroll") for (int mt = 0; mt < 4; mt++) \
    _Pragma("unroll") for (int nt = 0; nt < 4; nt++) { \
        const int p = nt >> 1, h = (nt & 1) * 2; \
        mma16816(acc[mt][nt], ahf[buf][mt], bhf[buf][p][h], bhf[buf][p][h + 1]); \
        mma16816(acc[mt][nt], ahf[buf][mt], blf[buf][p][h], blf[buf][p][h + 1]); \
        mma16816(acc[mt][nt], alf[buf][mt], bhf[buf][p][h], bhf[buf][p][h + 1]); \
    } }

    for (int c = 0; c < nch; c++) {
        cp_wait<NSTAGE - 2>();
        __syncthreads();
        // Issue the next chunk into the stage that was consumed last iteration.
        // The barrier above guarantees every warp is done reading it.
        if (c + NSTAGE - 1 < nch) ISSUE(c + NSTAGE - 1, (c + NSTAGE - 1) & (NSTAGE - 1));
        CP_COMMIT();

        const uint32_t stb = sbase + (c & (NSTAGE - 1)) * STAGEB;
        LOADFRAG(0, stb, 0);
        LOADFRAG(1, stb, 32);     // 16 bf16 = 32 bytes k-step offset
        DOMMA(0);
        DOMMA(1);
    }
#undef ISSUE
#undef LOADFRAG
#undef DOMMA

    // ------------------- epilogue -------------------
    float* Cfz = (EPI == EP_Q || EPI == EP_SC || EPI == EP_BIAS || EPI == EP_OUT)
                     ? Cf + (long long)z * sC : nullptr;
    __nv_bfloat16* Chz = (EPI == EP_Q || EPI == EP_HEAD || EPI == EP_SWISH)
                             ? Ch + (long long)z * sC : nullptr;
    __nv_bfloat16* Clz = (EPI == EP_Q || EPI == EP_HEAD || EPI == EP_SWISH)
                             ? Cl + (long long)z * sC : nullptr;
    const float* Eq = (EPI == EP_HEAD) ? E + (long long)z * sE : nullptr;
    const bool diag = (EPI == EP_SC) && (col0 == row0);

#pragma unroll
    for (int mt = 0; mt < 4; mt++) {
#pragma unroll
        for (int nt = 0; nt < 4; nt++) {
#pragma unroll
            for (int half = 0; half < 2; half++) {
                const int r = row0 + m0 + mt * 16 + (lane >> 2) + half * 8;
                const int cc = col0 + n0 + nt * 8 + (lane & 3) * 2;
                float v0 = acc[mt][nt][half * 2];
                float v1 = acc[mt][nt][half * 2 + 1];

                if (EPI == EP_SC) {
                    v0 *= 0.03125f; v1 *= 0.03125f;
                    if (diag) {
                        if (cc > r) v0 = NEGV;
                        if (cc + 1 > r) v1 = NEGV;
                    }
                    *reinterpret_cast<float2*>(&Cfz[(long long)r * N + cc]) =
                        make_float2(v0, v1);
                } else if (EPI == EP_BIAS) {
                    float2 bb = *reinterpret_cast<const float2*>(&E[cc]);
                    *reinterpret_cast<float2*>(&Cfz[(long long)r * N + cc]) =
                        make_float2(v0 + bb.x, v1 + bb.y);
                } else if (EPI == EP_OUT) {
                    *reinterpret_cast<float2*>(&Cfz[(long long)r * N + cc]) =
                        make_float2(v0, v1);
                } else {
                    if (EPI == EP_HEAD) {
                        float2 ee = *reinterpret_cast<const float2*>(
                            &Eq[(long long)r * N + cc]);
                        v0 += ee.x; v1 += ee.y;
                    }
                    if (EPI == EP_SWISH) {
                        v0 = v0 / (1.0f + expf(-v0));
                        v1 = v1 / (1.0f + expf(-v1));
                    }
                    if (EPI == EP_Q)
                        *reinterpret_cast<float2*>(&Cfz[(long long)r * N + cc]) =
                            make_float2(v0, v1);
                    __nv_bfloat16 h0, h1, l0, l1;
                    split_f(v0, h0, l0);
                    split_f(v1, h1, l1);
                    *reinterpret_cast<__nv_bfloat162*>(&Chz[(long long)r * N + cc]) =
                        __halves2bfloat162(h0, h1);
                    *reinterpret_cast<__nv_bfloat162*>(&Clz[(long long)r * N + cc]) =
                        __halves2bfloat162(l0, l1);
                }
            }
        }
    }
}

// ---------------------------------------------------------------------------
// Transpose + split: dst[c][r] = split(src[r][c]); optional sum over 8 heads
// ---------------------------------------------------------------------------
template <bool SUMH>
__global__ void tsplit(const float* __restrict__ S, __nv_bfloat16* __restrict__ Dh,
                       __nv_bfloat16* __restrict__ Dl, int R, int C,
                       long long sS, long long sD)
{
    __shared__ float t[32][33];
    const int tx = threadIdx.x, ty = threadIdx.y;
    const int c0 = blockIdx.x * 32, r0 = blockIdx.y * 32, z = blockIdx.z;
    const float* Sz = S + (long long)z * sS;
#pragma unroll
    for (int i = 0; i < 4; i++) {
        int r = r0 + ty + i * 8;
        float v;
        if (SUMH) {
            v = 0.f;
#pragma unroll
            for (int h = 0; h < 8; h++)
                v += S[(size_t)(h * 1024 + r) * C + c0 + tx];
        } else {
            v = Sz[(size_t)r * C + c0 + tx];
        }
        t[ty + i * 8][tx] = v;
    }
    __syncthreads();
#pragma unroll
    for (int i = 0; i < 4; i++) {
        int orow = c0 + ty + i * 8;
        float v = t[tx][ty + i * 8];
        __nv_bfloat16 h, l;
        split_f(v, h, l);
        Dh[(long long)z * sD + (size_t)orow * R + r0 + tx] = h;
        Dl[(long long)z * sD + (size_t)orow * R + r0 + tx] = l;
    }
}

// ---------------------------------------------------------------------------
// Elementwise split
// ---------------------------------------------------------------------------
__global__ void split_ew(const float* __restrict__ X, __nv_bfloat16* __restrict__ H,
                         __nv_bfloat16* __restrict__ L)
{
    size_t i = ((size_t)blockIdx.x * 256 + threadIdx.x);
    float4 v = reinterpret_cast<const float4*>(X)[i];
    __nv_bfloat16 h0, h1, h2, h3, l0, l1, l2, l3;
    split_f(v.x, h0, l0); split_f(v.y, h1, l1);
    split_f(v.z, h2, l2); split_f(v.w, h3, l3);
    reinterpret_cast<__nv_bfloat162*>(H)[i * 2]     = __halves2bfloat162(h0, h1);
    reinterpret_cast<__nv_bfloat162*>(H)[i * 2 + 1] = __halves2bfloat162(h2, h3);
    reinterpret_cast<__nv_bfloat162*>(L)[i * 2]     = __halves2bfloat162(l0, l1);
    reinterpret_cast<__nv_bfloat162*>(L)[i * 2 + 1] = __halves2bfloat162(l2, l3);
}

// ---------------------------------------------------------------------------
// Reductions
// ---------------------------------------------------------------------------
__device__ __forceinline__ float warpMax(float v) {
#pragma unroll
    for (int o = 16; o; o >>= 1) v = fmaxf(v, __shfl_xor_sync(0xffffffffu, v, o));
    return v;
}
__device__ __forceinline__ float warpSum(float v) {
#pragma unroll
    for (int o = 16; o; o >>= 1) v += __shfl_xor_sync(0xffffffffu, v, o);
    return v;
}

// Softmax over scores rows; writes split probs. One block per row (2048 cols).
__global__ __launch_bounds__(256) void softmax_split(
    const float* __restrict__ Sc, __nv_bfloat16* __restrict__ Ph,
    __nv_bfloat16* __restrict__ Pl)
{
    const float* row = Sc + (long long)blockIdx.x * SS;
    __nv_bfloat16* oh = Ph + (long long)blockIdx.x * SS;
    __nv_bfloat16* ol = Pl + (long long)blockIdx.x * SS;
    const int tid = threadIdx.x, lane = tid & 31, w = tid >> 5;
    __shared__ float red[32];

    float4 v0 = reinterpret_cast<const float4*>(row)[tid];
    float4 v1 = reinterpret_cast<const float4*>(row)[tid + 256];
    float m = fmaxf(fmaxf(fmaxf(v0.x, v0.y), fmaxf(v0.z, v0.w)),
                    fmaxf(fmaxf(v1.x, v1.y), fmaxf(v1.z, v1.w)));
    m = warpMax(m);
    if (lane == 0) red[w] = m;
    __syncthreads();
    if (tid < 32) { float x = (tid < 8) ? red[tid] : -3.4e38f; x = warpMax(x);
                    if (tid == 0) red[0] = x; }
    __syncthreads();
    m = red[0];
    __syncthreads();

    float e0x = expf(v0.x - m), e0y = expf(v0.y - m),
          e0z = expf(v0.z - m), e0w = expf(v0.w - m);
    float e1x = expf(v1.x - m), e1y = expf(v1.y - m),
          e1z = expf(v1.z - m), e1w = expf(v1.w - m);
    float s = e0x + e0y + e0z + e0w + e1x + e1y + e1z + e1w;
    s = warpSum(s);
    if (lane == 0) red[w] = s;
    __syncthreads();
    if (tid < 32) { float x = (tid < 8) ? red[tid] : 0.f; x = warpSum(x);
                    if (tid == 0) red[0] = x; }
    __syncthreads();
    const float inv = 1.0f / red[0];

    float p[8] = {e0x * inv, e0y * inv, e0z * inv, e0w * inv,
                  e1x * inv, e1y * inv, e1z * inv, e1w * inv};
    __nv_bfloat16 h[8], l[8];
#pragma unroll
    for (int u = 0; u < 8; u++) split_f(p[u], h[u], l[u]);
    __nv_bfloat162* phh = reinterpret_cast<__nv_bfloat162*>(oh);
    __nv_bfloat162* pll = reinterpret_cast<__nv_bfloat162*>(ol);
    phh[tid * 2]             = __halves2bfloat162(h[0], h[1]);
    phh[tid * 2 + 1]         = __halves2bfloat162(h[2], h[3]);
    phh[(tid + 256) * 2]     = __halves2bfloat162(h[4], h[5]);
    phh[(tid + 256) * 2 + 1] = __halves2bfloat162(h[6], h[7]);
    pll[tid * 2]             = __halves2bfloat162(l[0], l[1]);
    pll[tid * 2 + 1]         = __halves2bfloat162(l[2], l[3]);
    pll[(tid + 256) * 2]     = __halves2bfloat162(l[4], l[5]);
    pll[(tid + 256) * 2 + 1] = __halves2bfloat162(l[6], l[7]);
}

// LayerNorm -> split. One block per row (1024 cols).
__global__ __launch_bounds__(256) void ln_split(
    const float* __restrict__ Hf, __nv_bfloat16* __restrict__ Oh,
    __nv_bfloat16* __restrict__ Ol)
{
    const float* row = Hf + (long long)blockIdx.x * DD;
    __nv_bfloat16* oh = Oh + (long long)blockIdx.x * DD;
    __nv_bfloat16* ol = Ol + (long long)blockIdx.x * DD;
    const int tid = threadIdx.x, lane = tid & 31, w = tid >> 5;
    __shared__ float r1[32], r2[32];

    float4 v = reinterpret_cast<const float4*>(row)[tid];
    float s = v.x + v.y + v.z + v.w;
    float s2 = v.x * v.x + v.y * v.y + v.z * v.z + v.w * v.w;
    s = warpSum(s); s2 = warpSum(s2);
    if (lane == 0) { r1[w] = s; r2[w] = s2; }
    __syncthreads();
    if (tid < 32) {
        float a = (tid < 8) ? r1[tid] : 0.f;
        float b = (tid < 8) ? r2[tid] : 0.f;
        a = warpSum(a); b = warpSum(b);
        if (tid == 0) { r1[0] = a; r2[0] = b; }
    }
    __syncthreads();
    const float mean = r1[0] * (1.0f / DD);
    const float msq = r2[0] * (1.0f / DD);
    const float inv = rsqrtf(msq - mean * mean + EPSV);

    float y[4] = {(v.x - mean) * inv, (v.y - mean) * inv,
                  (v.z - mean) * inv, (v.w - mean) * inv};
    __nv_bfloat16 h[4], l[4];
#pragma unroll
    for (int u = 0; u < 4; u++) split_f(y[u], h[u], l[u]);
    reinterpret_cast<__nv_bfloat162*>(oh)[tid * 2]     = __halves2bfloat162(h[0], h[1]);
    reinterpret_cast<__nv_bfloat162*>(oh)[tid * 2 + 1] = __halves2bfloat162(h[2], h[3]);
    reinterpret_cast<__nv_bfloat162*>(ol)[tid * 2]     = __halves2bfloat162(l[0], l[1]);
    reinterpret_cast<__nv_bfloat162*>(ol)[tid * 2 + 1] = __halves2bfloat162(l[2], l[3]);
}

// ---------------------------------------------------------------------------
// Launch
// ---------------------------------------------------------------------------
extern "C" void kernel_launch(void* const* d_in, const int* in_sizes, int n_in,
                              void* d_out, int out_size)
{
    (void)in_sizes; (void)n_in; (void)out_size;
    const float* x     = (const float*)d_in[0];
    const float* wi    = (const float*)d_in[2];
    const float* okern = (const float*)d_in[3];
    const float* obias = (const float*)d_in[4];
    float* out = (float*)d_out;

    unsigned char* base;
    cudaGetSymbolAddress((void**)&base, g_scratch);
    float* qf  = (float*)(base + O_QF);
    float* sc  = (float*)(base + O_SC);
    float* hhf = (float*)(base + O_HHF);
    __nv_bfloat16* qh  = (__nv_bfloat16*)(base + O_QH);
    __nv_bfloat16* ql  = (__nv_bfloat16*)(base + O_QL);
    __nv_bfloat16* qTh = (__nv_bfloat16*)(base + O_QTH);
    __nv_bfloat16* qTl = (__nv_bfloat16*)(base + O_QTL);
    __nv_bfloat16* xh  = (__nv_bfloat16*)(base + O_XH);
    __nv_bfloat16* xl  = (__nv_bfloat16*)(base + O_XL);
    __nv_bfloat16* Pph = (__nv_bfloat16*)(base + O_PH);
    __nv_bfloat16* Ppl = (__nv_bfloat16*)(base + O_PL);
    __nv_bfloat16* hdh = (__nv_bfloat16*)(base + O_HDH);
    __nv_bfloat16* hdl = (__nv_bfloat16*)(base + O_HDL);
    __nv_bfloat16* hnh = (__nv_bfloat16*)(base + O_HNH);
    __nv_bfloat16* hnl = (__nv_bfloat16*)(base + O_HNL);
    __nv_bfloat16* fh  = (__nv_bfloat16*)(base + O_FH);
    __nv_bfloat16* fl  = (__nv_bfloat16*)(base + O_FL);
    __nv_bfloat16* wTh = (__nv_bfloat16*)(base + O_WTH);
    __nv_bfloat16* wTl = (__nv_bfloat16*)(base + O_WTL);
    __nv_bfloat16* wsh = (__nv_bfloat16*)(base + O_WSH);
    __nv_bfloat16* wsl = (__nv_bfloat16*)(base + O_WSL);

    cudaFuncSetAttribute(gemm_bb<EP_Q>,     cudaFuncAttributeMaxDynamicSharedMemorySize, GEMM_SMEM);
    cudaFuncSetAttribute(gemm_bb<EP_SC>,    cudaFuncAttributeMaxDynamicSharedMemorySize, GEMM_SMEM);
    cudaFuncSetAttribute(gemm_bb<EP_HEAD>,  cudaFuncAttributeMaxDynamicSharedMemorySize, GEMM_SMEM);
    cudaFuncSetAttribute(gemm_bb<EP_BIAS>,  cudaFuncAttributeMaxDynamicSharedMemorySize, GEMM_SMEM);
    cudaFuncSetAttribute(gemm_bb<EP_SWISH>, cudaFuncAttributeMaxDynamicSharedMemorySize, GEMM_SMEM);
    cudaFuncSetAttribute(gemm_bb<EP_OUT>,   cudaFuncAttributeMaxDynamicSharedMemorySize, GEMM_SMEM);

    const long long sSD = (long long)SS * DD;   // 2,097,152
    const long long sSS = (long long)SS * SS;   // 4,194,304
    dim3 tb(32, 8);

    // wi^T split, Wsum^T split, x split
    tsplit<false><<<dim3(32, 32, 1), tb>>>(wi, wTh, wTl, DD, DD, 0, 0);
    tsplit<true><<<dim3(32, 32, 1), tb>>>(okern, wsh, wsl, DD, DD, 0, 0);
    split_ew<<<(BSR * DD) / 1024, 256>>>(x, xh, xl);

    // q = x @ wi  (fp32 + split)
    gemm_bb<EP_Q><<<dim3(8, 32, 1), 256, GEMM_SMEM>>>(
        xh, xl, wTh, wTl, qf, qh, ql, nullptr, DD, DD, 0, 0, 0, 0, 0);

    // q^T split per batch
    tsplit<false><<<dim3(32, 64, 2), tb>>>(qf, qTh, qTl, SS, DD, sSD, sSD);

    // scores = causal((q @ q^T)/32)  fp32
    gemm_bb<EP_SC><<<dim3(16, 16, 2), 256, GEMM_SMEM>>>(
        qh, ql, qh, ql, sc, nullptr, nullptr, nullptr,
        DD, SS, sSD, sSD, sSS, 0, 1);

    // softmax -> split probs
    softmax_split<<<SB * SS, 256>>>(sc, Pph, Ppl);

    // head = q + P @ q  (split out; K truncated at diagonal)
    gemm_bb<EP_HEAD><<<dim3(8, 16, 2), 256, GEMM_SMEM>>>(
        Pph, Ppl, qTh, qTl, nullptr, hdh, hdl, qf,
        SS, DD, sSS, sSD, sSD, sSD, 2);

    // h = head @ Wsum + bias  fp32
    gemm_bb<EP_BIAS><<<dim3(8, 32, 1), 256, GEMM_SMEM>>>(
        hdh, hdl, wsh, wsl, hhf, nullptr, nullptr, obias,
        DD, DD, 0, 0, 0, 0, 0);

    // layernorm -> split
    ln_split<<<BSR, 256>>>(hhf, hnh, hnl);

    // f = swish(h @ wi)  (split out)
    gemm_bb<EP_SWISH><<<dim3(8, 32, 1), 256, GEMM_SMEM>>>(
        hnh, hnl, wTh, wTl, nullptr, fh, fl, nullptr,
        DD, DD, 0, 0, 0, 0, 0);

    // out = f @ wi  fp32
    gemm_bb<EP_OUT><<<dim3(8, 32, 1), 256, GEMM_SMEM>>>(
        fh, fl, wTh, wTl, out, nullptr, nullptr, nullptr,
        DD, DD, 0, 0, 0, 0, 0);
}

// round 5
// speedup vs baseline: 2.5119x; 1.0314x over previous
#include <cuda_runtime.h>
#include <cuda_bf16.h>
#include <stdint.h>
#include <math.h>

#define SB 2
#define SS 2048
#define DD 1024
#define BSR 4096
#define NEGV (-1e10f)
#define EPSV 1e-5f

// ---------------------------------------------------------------------------
// Scratch carve-out (one big device global; no allocation allowed)
// ---------------------------------------------------------------------------
__device__ __align__(256) unsigned char g_scratch[209715200ULL];  // 200 MB

#define O_QF   0ULL            // q fp32            [4096,1024]
#define O_QH   16777216ULL     // q hi bf16
#define O_QL   25165824ULL
#define O_QTH  33554432ULL     // qT hi bf16        [2][1024][2048]
#define O_QTL  41943040ULL
#define O_XH   50331648ULL     // x split
#define O_XL   58720256ULL
#define O_SC   67108864ULL     // scores fp32       [2][2048][2048]
#define O_PH   100663296ULL    // softmax probs split
#define O_PL   117440512ULL
#define O_HDH  134217728ULL    // head split
#define O_HDL  142606336ULL
#define O_HHF  150994944ULL    // h fp32 (pre-LN)
#define O_HNH  167772160ULL    // h split (post-LN)
#define O_HNL  176160768ULL
#define O_FH   184549376ULL    // swish output split
#define O_FL   192937984ULL
#define O_WTH  201326592ULL    // wi^T split        [1024,1024]
#define O_WTL  203423744ULL
#define O_WSH  205520896ULL    // Wsum^T split
#define O_WSL  207618048ULL

// ---------------------------------------------------------------------------
// Portable sm_80+ primitives: cp.async, ldmatrix, bf16 mma.sync
// ---------------------------------------------------------------------------
__device__ __forceinline__ uint32_t smem_u32(const void* p) {
    uint32_t a;
    asm("{ .reg .u64 t; cvta.to.shared.u64 t, %1; cvt.u32.u64 %0, t; }"
        : "=r"(a) : "l"(p));
    return a;
}
__device__ __forceinline__ void cp16(uint32_t s, const void* g) {
    asm volatile("cp.async.cg.shared.global [%0], [%1], 16;" :: "r"(s), "l"(g));
}
#define CP_COMMIT() asm volatile("cp.async.commit_group;" ::: "memory")
template <int N> __device__ __forceinline__ void cp_wait() {
    asm volatile("cp.async.wait_group %0;" :: "n"(N) : "memory");
}
__device__ __forceinline__ void ldsm4(uint32_t (&r)[4], uint32_t a) {
    asm volatile("ldmatrix.sync.aligned.m8n8.x4.shared.b16 {%0,%1,%2,%3}, [%4];"
                 : "=r"(r[0]), "=r"(r[1]), "=r"(r[2]), "=r"(r[3]) : "r"(a));
}
__device__ __forceinline__ void mma16816(float (&c)[4], const uint32_t (&a)[4],
                                         uint32_t b0, uint32_t b1) {
    asm volatile(
        "mma.sync.aligned.m16n8k16.row.col.f32.bf16.bf16.f32 "
        "{%0,%1,%2,%3}, {%4,%5,%6,%7}, {%8,%9}, {%0,%1,%2,%3};"
        : "+f"(c[0]), "+f"(c[1]), "+f"(c[2]), "+f"(c[3])
        : "r"(a[0]), "r"(a[1]), "r"(a[2]), "r"(a[3]), "r"(b0), "r"(b1));
}

__device__ __forceinline__ void split_f(float v, __nv_bfloat16& h, __nv_bfloat16& l) {
    h = __float2bfloat16(v);
    l = __float2bfloat16(v - __bfloat162float(h));
}

// ---------------------------------------------------------------------------
// GEMM: C[M,N] = A[M,K] @ B[N,K]^T, pre-split bf16 hi/lo, mma.sync HMMA.
// CTA tile 128x128, 8 warps (2m x 4n of 64x32), K-chunk 32, cp.async 2-stage,
// 2 CTAs/SM (occupancy is the binding constraint, not pipeline depth).
// ---------------------------------------------------------------------------
enum { EP_Q = 0, EP_SC = 1, EP_HEAD = 2, EP_BIAS = 3, EP_SWISH = 4, EP_OUT = 5 };

#define RPAD 40
#define MATB (128 * RPAD * 2)     // 10240 bytes per matrix tile
#define OFF_AH 0
#define OFF_AL (MATB)
#define OFF_BH (2 * MATB)
#define OFF_BL (3 * MATB)
#define STAGEB (4 * MATB)         // 40960
#define GEMM_SMEM (2 * STAGEB)    // 81920 -> two CTAs fit in 228KB

template <int EPI>
__global__ __launch_bounds__(256, 2) void gemm_bb(
    const __nv_bfloat16* __restrict__ Agh, const __nv_bfloat16* __restrict__ Agl,
    const __nv_bfloat16* __restrict__ Bgh, const __nv_bfloat16* __restrict__ Bgl,
    float* __restrict__ Cf, __nv_bfloat16* __restrict__ Ch,
    __nv_bfloat16* __restrict__ Cl, const float* __restrict__ E,
    int K, int N, long long sA, long long sB, long long sC, long long sE,
    int causal)
{
    extern __shared__ unsigned char smb[];

    const int tid = threadIdx.x;
    const int wid = tid >> 5;
    const int lane = tid & 31;
    const int row0 = blockIdx.y * 128;
    const int col0 = blockIdx.x * 128;
    const int z = blockIdx.z;

    // scores: tile entirely above diagonal -> NEG fill, no compute
    if (EPI == EP_SC && col0 > row0) {
        float* C = Cf + (long long)z * sC;
        float4 v = make_float4(NEGV, NEGV, NEGV, NEGV);
        for (int i = tid; i < 128 * 32; i += 256) {
            int r = i >> 5, c4 = (i & 31) * 4;
            *reinterpret_cast<float4*>(&C[(long long)(row0 + r) * N + col0 + c4]) = v;
        }
        return;
    }

    const __nv_bfloat16* Ah = Agh + (long long)z * sA;
    const __nv_bfloat16* Al = Agl + (long long)z * sA;
    const __nv_bfloat16* Bh = Bgh + (long long)z * sB;
    const __nv_bfloat16* Bl = Bgl + (long long)z * sB;

    const int kEnd = (causal == 2) ? min(K, row0 + 128) : K;
    const int nch = kEnd >> 5;

    const uint32_t sbase = smem_u32(smb);

    // ---- loader mapping: thread -> row tid>>1, two 16B quads (tid&1)*2+{0,1}
    const int ldr = tid >> 1;
    const int ldq = (tid & 1) * 2;
    const size_t aRow = (size_t)(row0 + ldr) * K;
    const size_t bRow = (size_t)(col0 + ldr) * K;
    const uint32_t sRow = (uint32_t)(ldr * (RPAD * 2));  // byte offset of row

    // ---- warp tile ----
    const int m0 = (wid >> 2) * 64;
    const int n0 = (wid & 3) * 32;

    // ldmatrix per-thread byte offsets (relative to stage base, ks=0)
    uint32_t aoff[4];
#pragma unroll
    for (int mt = 0; mt < 4; mt++)
        aoff[mt] = (uint32_t)((m0 + mt * 16 + (lane & 15)) * (RPAD * 2) +
                              ((lane >> 4) * 8) * 2);
    uint32_t boff[2];
#pragma unroll
    for (int p = 0; p < 2; p++)
        boff[p] = (uint32_t)((n0 + p * 16 + ((lane >> 4) << 3) + (lane & 7)) *
                                 (RPAD * 2) +
                             (((lane >> 3) & 1) * 8) * 2);

    float acc[4][4][4] = {};

#define ISSUE(c, st) { \
    const int kk = (c) * 32; \
    const uint32_t sb = sbase + (st) * STAGEB + sRow; \
    _Pragma("unroll") for (int u = 0; u < 2; u++) { \
        const int q = ldq + u; \
        cp16(sb + OFF_AH + q * 16, Ah + aRow + kk + q * 8); \
        cp16(sb + OFF_AL + q * 16, Al + aRow + kk + q * 8); \
        cp16(sb + OFF_BH + q * 16, Bh + bRow + kk + q * 8); \
        cp16(sb + OFF_BL + q * 16, Bl + bRow + kk + q * 8); \
    } }

    ISSUE(0, 0);
    CP_COMMIT();

    for (int c = 0; c < nch; c++) {
        if (c + 1 < nch) {
            ISSUE(c + 1, (c + 1) & 1);
            CP_COMMIT();
            cp_wait<1>();
        } else {
            cp_wait<0>();
        }
        __syncthreads();

        const uint32_t stb = sbase + (c & 1) * STAGEB;
#pragma unroll
        for (int ks = 0; ks < 2; ks++) {
            const uint32_t kso = (uint32_t)(ks * 32);
            uint32_t ahf[4][4], alf[4][4], bhf[2][4], blf[2][4];
#pragma unroll
            for (int mt = 0; mt < 4; mt++) {
                ldsm4(ahf[mt], stb + OFF_AH + aoff[mt] + kso);
                ldsm4(alf[mt], stb + OFF_AL + aoff[mt] + kso);
            }
#pragma unroll
            for (int p = 0; p < 2; p++) {
                ldsm4(bhf[p], stb + OFF_BH + boff[p] + kso);
                ldsm4(blf[p], stb + OFF_BL + boff[p] + kso);
            }
#pragma unroll
            for (int mt = 0; mt < 4; mt++)
#pragma unroll
                for (int nt = 0; nt < 4; nt++) {
                    const int p = nt >> 1, h = (nt & 1) * 2;
                    mma16816(acc[mt][nt], ahf[mt], bhf[p][h], bhf[p][h + 1]);
                    mma16816(acc[mt][nt], ahf[mt], blf[p][h], blf[p][h + 1]);
                    mma16816(acc[mt][nt], alf[mt], bhf[p][h], bhf[p][h + 1]);
                }
        }
        __syncthreads();
    }
#undef ISSUE

    // ------------------- epilogue -------------------
    float* Cfz = (EPI == EP_Q || EPI == EP_SC || EPI == EP_BIAS || EPI == EP_OUT)
                     ? Cf + (long long)z * sC : nullptr;
    __nv_bfloat16* Chz = (EPI == EP_Q || EPI == EP_HEAD || EPI == EP_SWISH)
                             ? Ch + (long long)z * sC : nullptr;
    __nv_bfloat16* Clz = (EPI == EP_Q || EPI == EP_HEAD || EPI == EP_SWISH)
                             ? Cl + (long long)z * sC : nullptr;
    const float* Eq = (EPI == EP_HEAD) ? E + (long long)z * sE : nullptr;
    const bool diag = (EPI == EP_SC) && (col0 == row0);

#pragma unroll
    for (int mt = 0; mt < 4; mt++) {
#pragma unroll
        for (int nt = 0; nt < 4; nt++) {
#pragma unroll
            for (int half = 0; half < 2; half++) {
                const int r = row0 + m0 + mt * 16 + (lane >> 2) + half * 8;
                const int cc = col0 + n0 + nt * 8 + (lane & 3) * 2;
                float v0 = acc[mt][nt][half * 2];
                float v1 = acc[mt][nt][half * 2 + 1];

                if (EPI == EP_SC) {
                    v0 *= 0.03125f; v1 *= 0.03125f;
                    if (diag) {
                        if (cc > r) v0 = NEGV;
                        if (cc + 1 > r) v1 = NEGV;
                    }
                    *reinterpret_cast<float2*>(&Cfz[(long long)r * N + cc]) =
                        make_float2(v0, v1);
                } else if (EPI == EP_BIAS) {
                    float2 bb = *reinterpret_cast<const float2*>(&E[cc]);
                    *reinterpret_cast<float2*>(&Cfz[(long long)r * N + cc]) =
                        make_float2(v0 + bb.x, v1 + bb.y);
                } else if (EPI == EP_OUT) {
                    *reinterpret_cast<float2*>(&Cfz[(long long)r * N + cc]) =
                        make_float2(v0, v1);
                } else {
                    if (EPI == EP_HEAD) {
                        float2 ee = *reinterpret_cast<const float2*>(
                            &Eq[(long long)r * N + cc]);
                        v0 += ee.x; v1 += ee.y;
                    }
                    if (EPI == EP_SWISH) {
                        v0 = v0 / (1.0f + expf(-v0));
                        v1 = v1 / (1.0f + expf(-v1));
                    }
                    if (EPI == EP_Q)
                        *reinterpret_cast<float2*>(&Cfz[(long long)r * N + cc]) =
                            make_float2(v0, v1);
                    __nv_bfloat16 h0, h1, l0, l1;
                    split_f(v0, h0, l0);
                    split_f(v1, h1, l1);
                    *reinterpret_cast<__nv_bfloat162*>(&Chz[(long long)r * N + cc]) =
                        __halves2bfloat162(h0, h1);
                    *reinterpret_cast<__nv_bfloat162*>(&Clz[(long long)r * N + cc]) =
                        __halves2bfloat162(l0, l1);
                }
            }
        }
    }
}

// ---------------------------------------------------------------------------
// Transpose + split: dst[c][r] = split(src[r][c]); optional sum over 8 heads
// ---------------------------------------------------------------------------
template <bool SUMH>
__global__ void tsplit(const float* __restrict__ S, __nv_bfloat16* __restrict__ Dh,
                       __nv_bfloat16* __restrict__ Dl, int R, int C,
                       long long sS, long long sD)
{
    __shared__ float t[32][33];
    const int tx = threadIdx.x, ty = threadIdx.y;
    const int c0 = blockIdx.x * 32, r0 = blockIdx.y * 32, z = blockIdx.z;
    const float* Sz = S + (long long)z * sS;
#pragma unroll
    for (int i = 0; i < 4; i++) {
        int r = r0 + ty + i * 8;
        float v;
        if (SUMH) {
            v = 0.f;
#pragma unroll
            for (int h = 0; h < 8; h++)
                v += S[(size_t)(h * 1024 + r) * C + c0 + tx];
        } else {
            v = Sz[(size_t)r * C + c0 + tx];
        }
        t[ty + i * 8][tx] = v;
    }
    __syncthreads();
#pragma unroll
    for (int i = 0; i < 4; i++) {
        int orow = c0 + ty + i * 8;
        float v = t[tx][ty + i * 8];
        __nv_bfloat16 h, l;
        split_f(v, h, l);
        Dh[(long long)z * sD + (size_t)orow * R + r0 + tx] = h;
        Dl[(long long)z * sD + (size_t)orow * R + r0 + tx] = l;
    }
}

// ---------------------------------------------------------------------------
// Elementwise split
// ---------------------------------------------------------------------------
__global__ void split_ew(const float* __restrict__ X, __nv_bfloat16* __restrict__ H,
                         __nv_bfloat16* __restrict__ L)
{
    size_t i = ((size_t)blockIdx.x * 256 + threadIdx.x);
    float4 v = reinterpret_cast<const float4*>(X)[i];
    __nv_bfloat16 h0, h1, h2, h3, l0, l1, l2, l3;
    split_f(v.x, h0, l0); split_f(v.y, h1, l1);
    split_f(v.z, h2, l2); split_f(v.w, h3, l3);
    reinterpret_cast<__nv_bfloat162*>(H)[i * 2]     = __halves2bfloat162(h0, h1);
    reinterpret_cast<__nv_bfloat162*>(H)[i * 2 + 1] = __halves2bfloat162(h2, h3);
    reinterpret_cast<__nv_bfloat162*>(L)[i * 2]     = __halves2bfloat162(l0, l1);
    reinterpret_cast<__nv_bfloat162*>(L)[i * 2 + 1] = __halves2bfloat162(l2, l3);
}

// ---------------------------------------------------------------------------
// Reductions
// ---------------------------------------------------------------------------
__device__ __forceinline__ float warpMax(float v) {
#pragma unroll
    for (int o = 16; o; o >>= 1) v = fmaxf(v, __shfl_xor_sync(0xffffffffu, v, o));
    return v;
}
__device__ __forceinline__ float warpSum(float v) {
#pragma unroll
    for (int o = 16; o; o >>= 1) v += __shfl_xor_sync(0xffffffffu, v, o);
    return v;
}

// Softmax over scores rows; writes split probs. One block per row (2048 cols).
__global__ __launch_bounds__(256) void softmax_split(
    const float* __restrict__ Sc, __nv_bfloat16* __restrict__ Ph,
    __nv_bfloat16* __restrict__ Pl)
{
    const float* row = Sc + (long long)blockIdx.x * SS;
    __nv_bfloat16* oh = Ph + (long long)blockIdx.x * SS;
    __nv_bfloat16* ol = Pl + (long long)blockIdx.x * SS;
    const int tid = threadIdx.x, lane = tid & 31, w = tid >> 5;
    __shared__ float red[32];

    float4 v0 = reinterpret_cast<const float4*>(row)[tid];
    float4 v1 = reinterpret_cast<const float4*>(row)[tid + 256];
    float m = fmaxf(fmaxf(fmaxf(v0.x, v0.y), fmaxf(v0.z, v0.w)),
                    fmaxf(fmaxf(v1.x, v1.y), fmaxf(v1.z, v1.w)));
    m = warpMax(m);
    if (lane == 0) red[w] = m;
    __syncthreads();
    if (tid < 32) { float x = (tid < 8) ? red[tid] : -3.4e38f; x = warpMax(x);
                    if (tid == 0) red[0] = x; }
    __syncthreads();
    m = red[0];
    __syncthreads();

    float e0x = expf(v0.x - m), e0y = expf(v0.y - m),
          e0z = expf(v0.z - m), e0w = expf(v0.w - m);
    float e1x = expf(v1.x - m), e1y = expf(v1.y - m),
          e1z = expf(v1.z - m), e1w = expf(v1.w - m);
    float s = e0x + e0y + e0z + e0w + e1x + e1y + e1z + e1w;
    s = warpSum(s);
    if (lane == 0) red[w] = s;
    __syncthreads();
    if (tid < 32) { float x = (tid < 8) ? red[tid] : 0.f; x = warpSum(x);
                    if (tid == 0) red[0] = x; }
    __syncthreads();
    const float inv = 1.0f / red[0];

    float p[8] = {e0x * inv, e0y * inv, e0z * inv, e0w * inv,
                  e1x * inv, e1y * inv, e1z * inv, e1w * inv};
    __nv_bfloat16 h[8], l[8];
#pragma unroll
    for (int u = 0; u < 8; u++) split_f(p[u], h[u], l[u]);
    __nv_bfloat162* phh = reinterpret_cast<__nv_bfloat162*>(oh);
    __nv_bfloat162* pll = reinterpret_cast<__nv_bfloat162*>(ol);
    phh[tid * 2]             = __halves2bfloat162(h[0], h[1]);
    phh[tid * 2 + 1]         = __halves2bfloat162(h[2], h[3]);
    phh[(tid + 256) * 2]     = __halves2bfloat162(h[4], h[5]);
    phh[(tid + 256) * 2 + 1] = __halves2bfloat162(h[6], h[7]);
    pll[tid * 2]             = __halves2bfloat162(l[0], l[1]);
    pll[tid * 2 + 1]         = __halves2bfloat162(l[2], l[3]);
    pll[(tid + 256) * 2]     = __halves2bfloat162(l[4], l[5]);
    pll[(tid + 256) * 2 + 1] = __halves2bfloat162(l[6], l[7]);
}

// LayerNorm -> split. One block per row (1024 cols).
__global__ __launch_bounds__(256) void ln_split(
    const float* __restrict__ Hf, __nv_bfloat16* __restrict__ Oh,
    __nv_bfloat16* __restrict__ Ol)
{
    const float* row = Hf + (long long)blockIdx.x * DD;
    __nv_bfloat16* oh = Oh + (long long)blockIdx.x * DD;
    __nv_bfloat16* ol = Ol + (long long)blockIdx.x * DD;
    const int tid = threadIdx.x, lane = tid & 31, w = tid >> 5;
    __shared__ float r1[32], r2[32];

    float4 v = reinterpret_cast<const float4*>(row)[tid];
    float s = v.x + v.y + v.z + v.w;
    float s2 = v.x * v.x + v.y * v.y + v.z * v.z + v.w * v.w;
    s = warpSum(s); s2 = warpSum(s2);
    if (lane == 0) { r1[w] = s; r2[w] = s2; }
    __syncthreads();
    if (tid < 32) {
        float a = (tid < 8) ? r1[tid] : 0.f;
        float b = (tid < 8) ? r2[tid] : 0.f;
        a = warpSum(a); b = warpSum(b);
        if (tid == 0) { r1[0] = a; r2[0] = b; }
    }
    __syncthreads();
    const float mean = r1[0] * (1.0f / DD);
    const float msq = r2[0] * (1.0f / DD);
    const float inv = rsqrtf(msq - mean * mean + EPSV);

    float y[4] = {(v.x - mean) * inv, (v.y - mean) * inv,
                  (v.z - mean) * inv, (v.w - mean) * inv};
    __nv_bfloat16 h[4], l[4];
#pragma unroll
    for (int u = 0; u < 4; u++) split_f(y[u], h[u], l[u]);
    reinterpret_cast<__nv_bfloat162*>(oh)[tid * 2]     = __halves2bfloat162(h[0], h[1]);
    reinterpret_cast<__nv_bfloat162*>(oh)[tid * 2 + 1] = __halves2bfloat162(h[2], h[3]);
    reinterpret_cast<__nv_bfloat162*>(ol)[tid * 2]     = __halves2bfloat162(l[0], l[1]);
    reinterpret_cast<__nv_bfloat162*>(ol)[tid * 2 + 1] = __halves2bfloat162(l[2], l[3]);
}

// ---------------------------------------------------------------------------
// Launch
// ---------------------------------------------------------------------------
extern "C" void kernel_launch(void* const* d_in, const int* in_sizes, int n_in,
                              void* d_out, int out_size)
{
    (void)in_sizes; (void)n_in; (void)out_size;
    const float* x     = (const float*)d_in[0];
    const float* wi    = (const float*)d_in[2];
    const float* okern = (const float*)d_in[3];
    const float* obias = (const float*)d_in[4];
    float* out = (float*)d_out;

    unsigned char* base;
    cudaGetSymbolAddress((void**)&base, g_scratch);
    float* qf  = (float*)(base + O_QF);
    float* sc  = (float*)(base + O_SC);
    float* hhf = (float*)(base + O_HHF);
    __nv_bfloat16* qh  = (__nv_bfloat16*)(base + O_QH);
    __nv_bfloat16* ql  = (__nv_bfloat16*)(base + O_QL);
    __nv_bfloat16* qTh = (__nv_bfloat16*)(base + O_QTH);
    __nv_bfloat16* qTl = (__nv_bfloat16*)(base + O_QTL);
    __nv_bfloat16* xh  = (__nv_bfloat16*)(base + O_XH);
    __nv_bfloat16* xl  = (__nv_bfloat16*)(base + O_XL);
    __nv_bfloat16* Pph = (__nv_bfloat16*)(base + O_PH);
    __nv_bfloat16* Ppl = (__nv_bfloat16*)(base + O_PL);
    __nv_bfloat16* hdh = (__nv_bfloat16*)(base + O_HDH);
    __nv_bfloat16* hdl = (__nv_bfloat16*)(base + O_HDL);
    __nv_bfloat16* hnh = (__nv_bfloat16*)(base + O_HNH);
    __nv_bfloat16* hnl = (__nv_bfloat16*)(base + O_HNL);
    __nv_bfloat16* fh  = (__nv_bfloat16*)(base + O_FH);
    __nv_bfloat16* fl  = (__nv_bfloat16*)(base + O_FL);
    __nv_bfloat16* wTh = (__nv_bfloat16*)(base + O_WTH);
    __nv_bfloat16* wTl = (__nv_bfloat16*)(base + O_WTL);
    __nv_bfloat16* wsh = (__nv_bfloat16*)(base + O_WSH);
    __nv_bfloat16* wsl = (__nv_bfloat16*)(base + O_WSL);

    cudaFuncSetAttribute(gemm_bb<EP_Q>,     cudaFuncAttributeMaxDynamicSharedMemorySize, GEMM_SMEM);
    cudaFuncSetAttribute(gemm_bb<EP_SC>,    cudaFuncAttributeMaxDynamicSharedMemorySize, GEMM_SMEM);
    cudaFuncSetAttribute(gemm_bb<EP_HEAD>,  cudaFuncAttributeMaxDynamicSharedMemorySize, GEMM_SMEM);
    cudaFuncSetAttribute(gemm_bb<EP_BIAS>,  cudaFuncAttributeMaxDynamicSharedMemorySize, GEMM_SMEM);
    cudaFuncSetAttribute(gemm_bb<EP_SWISH>, cudaFuncAttributeMaxDynamicSharedMemorySize, GEMM_SMEM);
    cudaFuncSetAttribute(gemm_bb<EP_OUT>,   cudaFuncAttributeMaxDynamicSharedMemorySize, GEMM_SMEM);

    const long long sSD = (long long)SS * DD;   // 2,097,152
    const long long sSS = (long long)SS * SS;   // 4,194,304
    dim3 tb(32, 8);

    // wi^T split, Wsum^T split, x split
    tsplit<false><<<dim3(32, 32, 1), tb>>>(wi, wTh, wTl, DD, DD, 0, 0);
    tsplit<true><<<dim3(32, 32, 1), tb>>>(okern, wsh, wsl, DD, DD, 0, 0);
    split_ew<<<(BSR * DD) / 1024, 256>>>(x, xh, xl);

    // q = x @ wi  (fp32 + split)
    gemm_bb<EP_Q><<<dim3(8, 32, 1), 256, GEMM_SMEM>>>(
        xh, xl, wTh, wTl, qf, qh, ql, nullptr, DD, DD, 0, 0, 0, 0, 0);

    // q^T split per batch
    tsplit<false><<<dim3(32, 64, 2), tb>>>(qf, qTh, qTl, SS, DD, sSD, sSD);

    // scores = causal((q @ q^T)/32)  fp32
    gemm_bb<EP_SC><<<dim3(16, 16, 2), 256, GEMM_SMEM>>>(
        qh, ql, qh, ql, sc, nullptr, nullptr, nullptr,
        DD, SS, sSD, sSD, sSS, 0, 1);

    // softmax -> split probs
    softmax_split<<<SB * SS, 256>>>(sc, Pph, Ppl);

    // head = q + P @ q  (split out; K truncated at diagonal)
    gemm_bb<EP_HEAD><<<dim3(8, 16, 2), 256, GEMM_SMEM>>>(
        Pph, Ppl, qTh, qTl, nullptr, hdh, hdl, qf,
        SS, DD, sSS, sSD, sSD, sSD, 2);

    // h = head @ Wsum + bias  fp32
    gemm_bb<EP_BIAS><<<dim3(8, 32, 1), 256, GEMM_SMEM>>>(
        hdh, hdl, wsh, wsl, hhf, nullptr, nullptr, obias,
        DD, DD, 0, 0, 0, 0, 0);

    // layernorm -> split
    ln_split<<<BSR, 256>>>(hhf, hnh, hnl);

    // f = swish(h @ wi)  (split out)
    gemm_bb<EP_SWISH><<<dim3(8, 32, 1), 256, GEMM_SMEM>>>(
        hnh, hnl, wTh, wTl, nullptr, fh, fl, nullptr,
        DD, DD, 0, 0, 0, 0, 0);

    // out = f @ wi  fp32
    gemm_bb<EP_OUT><<<dim3(8, 32, 1), 256, GEMM_SMEM>>>(
        fh, fl, wTh, wTl, out, nullptr, nullptr, nullptr,
        DD, DD, 0, 0, 0, 0, 0);
}

// round 6
// speedup vs baseline: 2.6016x; 1.0357x over previous
#include <cuda_runtime.h>
#include <cuda_bf16.h>
#include <stdint.h>
#include <math.h>

#define SB 2
#define SS 2048
#define DD 1024
#define BSR 4096
#define NEGV (-1e10f)
#define EPSV 1e-5f

// ---------------------------------------------------------------------------
// Scratch carve-out (one big device global; no allocation allowed)
// ---------------------------------------------------------------------------
__device__ __align__(256) unsigned char g_scratch[209715200ULL];  // 200 MB

#define O_QF   0ULL            // q fp32            [4096,1024]
#define O_QH   16777216ULL     // q hi bf16
#define O_QL   25165824ULL
#define O_XH   50331648ULL     // x split
#define O_XL   58720256ULL
#define O_SC   67108864ULL     // scores fp32       [2][2048][2048]
#define O_PH   100663296ULL    // softmax probs split
#define O_PL   117440512ULL
#define O_HDH  134217728ULL    // head split
#define O_HDL  142606336ULL
#define O_HHF  150994944ULL    // h fp32 (pre-LN)
#define O_HNH  167772160ULL    // h split (post-LN)
#define O_HNL  176160768ULL
#define O_FH   184549376ULL    // swish output split
#define O_FL   192937984ULL
#define O_WTH  201326592ULL    // wi^T split        [1024,1024]
#define O_WTL  203423744ULL
#define O_WSH  205520896ULL    // Wsum^T split
#define O_WSL  207618048ULL

// ---------------------------------------------------------------------------
// Portable sm_80+ primitives: cp.async, ldmatrix, bf16 mma.sync
// ---------------------------------------------------------------------------
__device__ __forceinline__ uint32_t smem_u32(const void* p) {
    uint32_t a;
    asm("{ .reg .u64 t; cvta.to.shared.u64 t, %1; cvt.u32.u64 %0, t; }"
        : "=r"(a) : "l"(p));
    return a;
}
__device__ __forceinline__ void cp16(uint32_t s, const void* g) {
    asm volatile("cp.async.cg.shared.global [%0], [%1], 16;" :: "r"(s), "l"(g));
}
#define CP_COMMIT() asm volatile("cp.async.commit_group;" ::: "memory")
template <int N> __device__ __forceinline__ void cp_wait() {
    asm volatile("cp.async.wait_group %0;" :: "n"(N) : "memory");
}
__device__ __forceinline__ void ldsm4(uint32_t (&r)[4], uint32_t a) {
    asm volatile("ldmatrix.sync.aligned.m8n8.x4.shared.b16 {%0,%1,%2,%3}, [%4];"
                 : "=r"(r[0]), "=r"(r[1]), "=r"(r[2]), "=r"(r[3]) : "r"(a));
}
__device__ __forceinline__ void ldsm4t(uint32_t (&r)[4], uint32_t a) {
    asm volatile("ldmatrix.sync.aligned.m8n8.x4.trans.shared.b16 {%0,%1,%2,%3}, [%4];"
                 : "=r"(r[0]), "=r"(r[1]), "=r"(r[2]), "=r"(r[3]) : "r"(a));
}
__device__ __forceinline__ void mma16816(float (&c)[4], const uint32_t (&a)[4],
                                         uint32_t b0, uint32_t b1) {
    asm volatile(
        "mma.sync.aligned.m16n8k16.row.col.f32.bf16.bf16.f32 "
        "{%0,%1,%2,%3}, {%4,%5,%6,%7}, {%8,%9}, {%0,%1,%2,%3};"
        : "+f"(c[0]), "+f"(c[1]), "+f"(c[2]), "+f"(c[3])
        : "r"(a[0]), "r"(a[1]), "r"(a[2]), "r"(a[3]), "r"(b0), "r"(b1));
}

__device__ __forceinline__ void split_f(float v, __nv_bfloat16& h, __nv_bfloat16& l) {
    h = __float2bfloat16(v);
    l = __float2bfloat16(v - __bfloat162float(h));
}

// ---------------------------------------------------------------------------
// GEMM: C[M,N] = A[M,K] @ B^T, pre-split bf16 hi/lo, mma.sync HMMA.
// B layout: TRB=0 -> B stored [N,K] (K-major rows). TRB=1 -> B stored [K,N]
// (read with ldmatrix.trans; used for PV so q needs no transpose).
// CTA tile 128x128, 8 warps (2m x 4n of 64x32), K-chunk 32, 2-stage, 2 CTA/SM.
// ---------------------------------------------------------------------------
enum { EP_Q = 0, EP_SC = 1, EP_HEAD = 2, EP_BIAS = 3, EP_SWISH = 4, EP_OUT = 5 };

#define RPAD 40
#define MATB (128 * RPAD * 2)       // 10240 bytes: A tiles + non-trans B tiles
#define BTROW 272                   // trans-B row bytes: 128 bf16 + 8 pad
#define BTMATB (32 * BTROW)         // 8704 bytes per trans-B matrix
#define OFF_AH 0
#define OFF_AL (MATB)
#define OFF_BH (2 * MATB)
#define GEMM_SMEM 81920

template <int EPI, int TRB>
__global__ __launch_bounds__(256, 2) void gemm_bb(
    const __nv_bfloat16* __restrict__ Agh, const __nv_bfloat16* __restrict__ Agl,
    const __nv_bfloat16* __restrict__ Bgh, const __nv_bfloat16* __restrict__ Bgl,
    float* __restrict__ Cf, __nv_bfloat16* __restrict__ Ch,
    __nv_bfloat16* __restrict__ Cl, const float* __restrict__ E,
    int K, int N, long long sA, long long sB, long long sC, long long sE,
    int causal)
{
    extern __shared__ unsigned char smb[];
    constexpr int BMATB = TRB ? BTMATB : MATB;
    constexpr int STAGEB = 2 * MATB + 2 * BMATB;

    const int tid = threadIdx.x;
    const int wid = tid >> 5;
    const int lane = tid & 31;
    const int z = blockIdx.z;

    int bi = blockIdx.y, bj = blockIdx.x;
    if (EPI == EP_SC) {
        // triangular decode: blockIdx.x in [0,136) -> (bi >= bj)
        int xx = blockIdx.x;
        bi = (int)((sqrtf(8.0f * xx + 1.0f) - 1.0f) * 0.5f);
        while ((bi + 1) * (bi + 2) / 2 <= xx) bi++;
        while (bi * (bi + 1) / 2 > xx) bi--;
        bj = xx - bi * (bi + 1) / 2;
    }
    const int row0 = bi * 128;
    const int col0 = bj * 128;

    const __nv_bfloat16* Ah = Agh + (long long)z * sA;
    const __nv_bfloat16* Al = Agl + (long long)z * sA;
    const __nv_bfloat16* Bh = Bgh + (long long)z * sB;
    const __nv_bfloat16* Bl = Bgl + (long long)z * sB;

    const int kEnd = (causal == 2) ? min(K, row0 + 128) : K;
    const int nch = kEnd >> 5;

    const uint32_t sbase = smem_u32(smb);

    // ---- A loader: thread -> row tid>>1, two 16B quads (tid&1)*2+{0,1}
    const int ldr = tid >> 1;
    const int ldq = (tid & 1) * 2;
    const size_t aRow = (size_t)(row0 + ldr) * K;
    const size_t bRow = (size_t)(col0 + ldr) * K;     // non-trans only
    const uint32_t sRow = (uint32_t)(ldr * (RPAD * 2));

    // ---- warp tile ----
    const int m0 = (wid >> 2) * 64;
    const int n0 = (wid & 3) * 32;

    uint32_t aoff[4];
#pragma unroll
    for (int mt = 0; mt < 4; mt++)
        aoff[mt] = (uint32_t)((m0 + mt * 16 + (lane & 15)) * (RPAD * 2) +
                              ((lane >> 4) * 8) * 2);
    // B ldmatrix offsets
    uint32_t boff[2];
    if (!TRB) {
#pragma unroll
        for (int p = 0; p < 2; p++)
            boff[p] = (uint32_t)((n0 + p * 16 + ((lane >> 4) << 3) + (lane & 7)) *
                                     (RPAD * 2) +
                                 (((lane >> 3) & 1) * 8) * 2);
    } else {
        // trans: lane -> k-row and n-col of the [K=32, N=128] tile
        const int kr = ((lane >> 3) & 1) * 8 + (lane & 7);
#pragma unroll
        for (int p = 0; p < 2; p++) {
            const int nc = n0 + p * 16 + (lane >> 4) * 8;
            boff[p] = (uint32_t)(kr * BTROW + nc * 2);
        }
    }

    float acc[4][4][4] = {};

#define ISSUE(c, st) { \
    const int kk = (c) * 32; \
    const uint32_t sb = sbase + (st) * STAGEB; \
    _Pragma("unroll") for (int u = 0; u < 2; u++) { \
        const int q = ldq + u; \
        cp16(sb + OFF_AH + sRow + q * 16, Ah + aRow + kk + q * 8); \
        cp16(sb + OFF_AL + sRow + q * 16, Al + aRow + kk + q * 8); \
        if (!TRB) { \
            cp16(sb + OFF_BH + sRow + q * 16, Bh + bRow + kk + q * 8); \
            cp16(sb + OFF_BH + BMATB + sRow + q * 16, Bl + bRow + kk + q * 8); \
        } else { \
            const int qi = tid * 2 + u; \
            const int brr = qi >> 4, bqc = qi & 15; \
            const size_t g = (size_t)(kk + brr) * N + col0 + bqc * 8; \
            const uint32_t s = OFF_BH + (uint32_t)(brr * BTROW + bqc * 16); \
            cp16(sb + s, Bh + g); \
            cp16(sb + BMATB + s, Bl + g); \
        } \
    } }

    ISSUE(0, 0);
    CP_COMMIT();

    for (int c = 0; c < nch; c++) {
        if (c + 1 < nch) {
            ISSUE(c + 1, (c + 1) & 1);
            CP_COMMIT();
            cp_wait<1>();
        } else {
            cp_wait<0>();
        }
        __syncthreads();

        const uint32_t stb = sbase + (c & 1) * STAGEB;
#pragma unroll
        for (int ks = 0; ks < 2; ks++) {
            const uint32_t ksoA = (uint32_t)(ks * 32);
            const uint32_t ksoB = TRB ? (uint32_t)(ks * 16 * BTROW)
                                      : (uint32_t)(ks * 32);
            uint32_t ahf[4][4], alf[4][4], bhf[2][4], blf[2][4];
#pragma unroll
            for (int mt = 0; mt < 4; mt++) {
                ldsm4(ahf[mt], stb + OFF_AH + aoff[mt] + ksoA);
                ldsm4(alf[mt], stb + OFF_AL + aoff[mt] + ksoA);
            }
#pragma unroll
            for (int p = 0; p < 2; p++) {
                if (!TRB) {
                    ldsm4(bhf[p], stb + OFF_BH + boff[p] + ksoB);
                    ldsm4(blf[p], stb + OFF_BH + BMATB + boff[p] + ksoB);
                } else {
                    ldsm4t(bhf[p], stb + OFF_BH + boff[p] + ksoB);
                    ldsm4t(blf[p], stb + OFF_BH + BMATB + boff[p] + ksoB);
                }
            }
#pragma unroll
            for (int mt = 0; mt < 4; mt++)
#pragma unroll
                for (int nt = 0; nt < 4; nt++) {
                    const int p = nt >> 1, h = (nt & 1) * 2;
                    mma16816(acc[mt][nt], ahf[mt], bhf[p][h], bhf[p][h + 1]);
                    mma16816(acc[mt][nt], ahf[mt], blf[p][h], blf[p][h + 1]);
                    mma16816(acc[mt][nt], alf[mt], bhf[p][h], bhf[p][h + 1]);
                }
        }
        __syncthreads();
    }
#undef ISSUE

    // ------------------- epilogue -------------------
    float* Cfz = (EPI == EP_Q || EPI == EP_SC || EPI == EP_BIAS || EPI == EP_OUT)
                     ? Cf + (long long)z * sC : nullptr;
    __nv_bfloat16* Chz = (EPI == EP_Q || EPI == EP_HEAD || EPI == EP_SWISH)
                             ? Ch + (long long)z * sC : nullptr;
    __nv_bfloat16* Clz = (EPI == EP_Q || EPI == EP_HEAD || EPI == EP_SWISH)
                             ? Cl + (long long)z * sC : nullptr;
    const float* Eq = (EPI == EP_HEAD) ? E + (long long)z * sE : nullptr;
    const bool diag = (EPI == EP_SC) && (col0 == row0);

#pragma unroll
    for (int mt = 0; mt < 4; mt++) {
#pragma unroll
        for (int nt = 0; nt < 4; nt++) {
#pragma unroll
            for (int half = 0; half < 2; half++) {
                const int r = row0 + m0 + mt * 16 + (lane >> 2) + half * 8;
                const int cc = col0 + n0 + nt * 8 + (lane & 3) * 2;
                float v0 = acc[mt][nt][half * 2];
                float v1 = acc[mt][nt][half * 2 + 1];

                if (EPI == EP_SC) {
                    // skip stores entirely above the diagonal (never read)
                    if (!diag || cc <= r) {
                        v0 *= 0.03125f; v1 *= 0.03125f;
                        *reinterpret_cast<float2*>(&Cfz[(long long)r * N + cc]) =
                            make_float2(v0, v1);
                    }
                } else if (EPI == EP_BIAS) {
                    float2 bb = *reinterpret_cast<const float2*>(&E[cc]);
                    *reinterpret_cast<float2*>(&Cfz[(long long)r * N + cc]) =
                        make_float2(v0 + bb.x, v1 + bb.y);
                } else if (EPI == EP_OUT) {
                    *reinterpret_cast<float2*>(&Cfz[(long long)r * N + cc]) =
                        make_float2(v0, v1);
                } else {
                    if (EPI == EP_HEAD) {
                        float2 ee = *reinterpret_cast<const float2*>(
                            &Eq[(long long)r * N + cc]);
                        v0 += ee.x; v1 += ee.y;
                    }
                    if (EPI == EP_SWISH) {
                        v0 = v0 / (1.0f + expf(-v0));
                        v1 = v1 / (1.0f + expf(-v1));
                    }
                    if (EPI == EP_Q)
                        *reinterpret_cast<float2*>(&Cfz[(long long)r * N + cc]) =
                            make_float2(v0, v1);
                    __nv_bfloat16 h0, h1, l0, l1;
                    split_f(v0, h0, l0);
                    split_f(v1, h1, l1);
                    *reinterpret_cast<__nv_bfloat162*>(&Chz[(long long)r * N + cc]) =
                        __halves2bfloat162(h0, h1);
                    *reinterpret_cast<__nv_bfloat162*>(&Clz[(long long)r * N + cc]) =
                        __halves2bfloat162(l0, l1);
                }
            }
        }
    }
}

// ---------------------------------------------------------------------------
// Transpose + split: dst[c][r] = split(src[r][c]); optional sum over 8 heads
// ---------------------------------------------------------------------------
template <bool SUMH>
__global__ void tsplit(const float* __restrict__ S, __nv_bfloat16* __restrict__ Dh,
                       __nv_bfloat16* __restrict__ Dl, int R, int C,
                       long long sS, long long sD)
{
    __shared__ float t[32][33];
    const int tx = threadIdx.x, ty = threadIdx.y;
    const int c0 = blockIdx.x * 32, r0 = blockIdx.y * 32, z = blockIdx.z;
    const float* Sz = S + (long long)z * sS;
#pragma unroll
    for (int i = 0; i < 4; i++) {
        int r = r0 + ty + i * 8;
        float v;
        if (SUMH) {
            v = 0.f;
#pragma unroll
            for (int h = 0; h < 8; h++)
                v += S[(size_t)(h * 1024 + r) * C + c0 + tx];
        } else {
            v = Sz[(size_t)r * C + c0 + tx];
        }
        t[ty + i * 8][tx] = v;
    }
    __syncthreads();
#pragma unroll
    for (int i = 0; i < 4; i++) {
        int orow = c0 + ty + i * 8;
        float v = t[tx][ty + i * 8];
        __nv_bfloat16 h, l;
        split_f(v, h, l);
        Dh[(long long)z * sD + (size_t)orow * R + r0 + tx] = h;
        Dl[(long long)z * sD + (size_t)orow * R + r0 + tx] = l;
    }
}

// ---------------------------------------------------------------------------
// Elementwise split
// ---------------------------------------------------------------------------
__global__ void split_ew(const float* __restrict__ X, __nv_bfloat16* __restrict__ H,
                         __nv_bfloat16* __restrict__ L)
{
    size_t i = ((size_t)blockIdx.x * 256 + threadIdx.x);
    float4 v = reinterpret_cast<const float4*>(X)[i];
    __nv_bfloat16 h0, h1, h2, h3, l0, l1, l2, l3;
    split_f(v.x, h0, l0); split_f(v.y, h1, l1);
    split_f(v.z, h2, l2); split_f(v.w, h3, l3);
    reinterpret_cast<__nv_bfloat162*>(H)[i * 2]     = __halves2bfloat162(h0, h1);
    reinterpret_cast<__nv_bfloat162*>(H)[i * 2 + 1] = __halves2bfloat162(h2, h3);
    reinterpret_cast<__nv_bfloat162*>(L)[i * 2]     = __halves2bfloat162(l0, l1);
    reinterpret_cast<__nv_bfloat162*>(L)[i * 2 + 1] = __halves2bfloat162(l2, l3);
}

// ---------------------------------------------------------------------------
// Reductions
// ---------------------------------------------------------------------------
__device__ __forceinline__ float warpMax(float v) {
#pragma unroll
    for (int o = 16; o; o >>= 1) v = fmaxf(v, __shfl_xor_sync(0xffffffffu, v, o));
    return v;
}
__device__ __forceinline__ float warpSum(float v) {
#pragma unroll
    for (int o = 16; o; o >>= 1) v += __shfl_xor_sync(0xffffffffu, v, o);
    return v;
}

// Causal softmax over scores rows; writes split probs only for the K range
// the PV GEMM reads (cols < kLim = ceil((r+1)/128)*128). One block per row.
__global__ __launch_bounds__(256) void softmax_split(
    const float* __restrict__ Sc, __nv_bfloat16* __restrict__ Ph,
    __nv_bfloat16* __restrict__ Pl)
{
    const int r = blockIdx.x & (SS - 1);
    const int kLim = ((r >> 7) + 1) << 7;
    const float* row = Sc + (long long)blockIdx.x * SS;
    __nv_bfloat16* oh = Ph + (long long)blockIdx.x * SS;
    __nv_bfloat16* ol = Pl + (long long)blockIdx.x * SS;
    const int tid = threadIdx.x, lane = tid & 31, w = tid >> 5;
    __shared__ float red[32];

    // two float4 slots per thread: cols 4*tid.. and 1024 + 4*tid..
    const int c0 = tid * 4;
    const int c1 = 1024 + tid * 4;
    float4 v0 = make_float4(NEGV, NEGV, NEGV, NEGV);
    float4 v1 = make_float4(NEGV, NEGV, NEGV, NEGV);
    if (c0 < kLim) v0 = reinterpret_cast<const float4*>(row)[tid];
    if (c1 < kLim) v1 = reinterpret_cast<const float4*>(row)[tid + 256];

    float m = -3.4e38f;
    if (c0 + 0 <= r) m = fmaxf(m, v0.x);
    if (c0 + 1 <= r) m = fmaxf(m, v0.y);
    if (c0 + 2 <= r) m = fmaxf(m, v0.z);
    if (c0 + 3 <= r) m = fmaxf(m, v0.w);
    if (c1 + 0 <= r) m = fmaxf(m, v1.x);
    if (c1 + 1 <= r) m = fmaxf(m, v1.y);
    if (c1 + 2 <= r) m = fmaxf(m, v1.z);
    if (c1 + 3 <= r) m = fmaxf(m, v1.w);
    m = warpMax(m);
    if (lane == 0) red[w] = m;
    __syncthreads();
    if (tid < 32) { float x = (tid < 8) ? red[tid] : -3.4e38f; x = warpMax(x);
                    if (tid == 0) red[0] = x; }
    __syncthreads();
    m = red[0];
    __syncthreads();

    float e[8];
    e[0] = (c0 + 0 <= r) ? expf(v0.x - m) : 0.f;
    e[1] = (c0 + 1 <= r) ? expf(v0.y - m) : 0.f;
    e[2] = (c0 + 2 <= r) ? expf(v0.z - m) : 0.f;
    e[3] = (c0 + 3 <= r) ? expf(v0.w - m) : 0.f;
    e[4] = (c1 + 0 <= r) ? expf(v1.x - m) : 0.f;
    e[5] = (c1 + 1 <= r) ? expf(v1.y - m) : 0.f;
    e[6] = (c1 + 2 <= r) ? expf(v1.z - m) : 0.f;
    e[7] = (c1 + 3 <= r) ? expf(v1.w - m) : 0.f;
    float s = e[0] + e[1] + e[2] + e[3] + e[4] + e[5] + e[6] + e[7];
    s = warpSum(s);
    if (lane == 0) red[w] = s;
    __syncthreads();
    if (tid < 32) { float x = (tid < 8) ? red[tid] : 0.f; x = warpSum(x);
                    if (tid == 0) red[0] = x; }
    __syncthreads();
    const float inv = 1.0f / red[0];

    __nv_bfloat16 h[8], l[8];
#pragma unroll
    for (int u = 0; u < 8; u++) split_f(e[u] * inv, h[u], l[u]);
    __nv_bfloat162* phh = reinterpret_cast<__nv_bfloat162*>(oh);
    __nv_bfloat162* pll = reinterpret_cast<__nv_bfloat162*>(ol);
    if (c0 < kLim) {
        phh[tid * 2]     = __halves2bfloat162(h[0], h[1]);
        phh[tid * 2 + 1] = __halves2bfloat162(h[2], h[3]);
        pll[tid * 2]     = __halves2bfloat162(l[0], l[1]);
        pll[tid * 2 + 1] = __halves2bfloat162(l[2], l[3]);
    }
    if (c1 < kLim) {
        phh[(tid + 256) * 2]     = __halves2bfloat162(h[4], h[5]);
        phh[(tid + 256) * 2 + 1] = __halves2bfloat162(h[6], h[7]);
        pll[(tid + 256) * 2]     = __halves2bfloat162(l[4], l[5]);
        pll[(tid + 256) * 2 + 1] = __halves2bfloat162(l[6], l[7]);
    }
}

// LayerNorm -> split. One block per row (1024 cols).
__global__ __launch_bounds__(256) void ln_split(
    const float* __restrict__ Hf, __nv_bfloat16* __restrict__ Oh,
    __nv_bfloat16* __restrict__ Ol)
{
    const float* row = Hf + (long long)blockIdx.x * DD;
    __nv_bfloat16* oh = Oh + (long long)blockIdx.x * DD;
    __nv_bfloat16* ol = Ol + (long long)blockIdx.x * DD;
    const int tid = threadIdx.x, lane = tid & 31, w = tid >> 5;
    __shared__ float r1[32], r2[32];

    float4 v = reinterpret_cast<const float4*>(row)[tid];
    float s = v.x + v.y + v.z + v.w;
    float s2 = v.x * v.x + v.y * v.y + v.z * v.z + v.w * v.w;
    s = warpSum(s); s2 = warpSum(s2);
    if (lane == 0) { r1[w] = s; r2[w] = s2; }
    __syncthreads();
    if (tid < 32) {
        float a = (tid < 8) ? r1[tid] : 0.f;
        float b = (tid < 8) ? r2[tid] : 0.f;
        a = warpSum(a); b = warpSum(b);
        if (tid == 0) { r1[0] = a; r2[0] = b; }
    }
    __syncthreads();
    const float mean = r1[0] * (1.0f / DD);
    const float msq = r2[0] * (1.0f / DD);
    const float inv = rsqrtf(msq - mean * mean + EPSV);

    float y[4] = {(v.x - mean) * inv, (v.y - mean) * inv,
                  (v.z - mean) * inv, (v.w - mean) * inv};
    __nv_bfloat16 h[4], l[4];
#pragma unroll
    for (int u = 0; u < 4; u++) split_f(y[u], h[u], l[u]);
    reinterpret_cast<__nv_bfloat162*>(oh)[tid * 2]     = __halves2bfloat162(h[0], h[1]);
    reinterpret_cast<__nv_bfloat162*>(oh)[tid * 2 + 1] = __halves2bfloat162(h[2], h[3]);
    reinterpret_cast<__nv_bfloat162*>(ol)[tid * 2]     = __halves2bfloat162(l[0], l[1]);
    reinterpret_cast<__nv_bfloat162*>(ol)[tid * 2 + 1] = __halves2bfloat162(l[2], l[3]);
}

// ---------------------------------------------------------------------------
// Launch
// ---------------------------------------------------------------------------
extern "C" void kernel_launch(void* const* d_in, const int* in_sizes, int n_in,
                              void* d_out, int out_size)
{
    (void)in_sizes; (void)n_in; (void)out_size;
    const float* x     = (const float*)d_in[0];
    const float* wi    = (const float*)d_in[2];
    const float* okern = (const float*)d_in[3];
    const float* obias = (const float*)d_in[4];
    float* out = (float*)d_out;

    unsigned char* base;
    cudaGetSymbolAddress((void**)&base, g_scratch);
    float* qf  = (float*)(base + O_QF);
    float* sc  = (float*)(base + O_SC);
    float* hhf = (float*)(base + O_HHF);
    __nv_bfloat16* qh  = (__nv_bfloat16*)(base + O_QH);
    __nv_bfloat16* ql  = (__nv_bfloat16*)(base + O_QL);
    __nv_bfloat16* xh  = (__nv_bfloat16*)(base + O_XH);
    __nv_bfloat16* xl  = (__nv_bfloat16*)(base + O_XL);
    __nv_bfloat16* Pph = (__nv_bfloat16*)(base + O_PH);
    __nv_bfloat16* Ppl = (__nv_bfloat16*)(base + O_PL);
    __nv_bfloat16* hdh = (__nv_bfloat16*)(base + O_HDH);
    __nv_bfloat16* hdl = (__nv_bfloat16*)(base + O_HDL);
    __nv_bfloat16* hnh = (__nv_bfloat16*)(base + O_HNH);
    __nv_bfloat16* hnl = (__nv_bfloat16*)(base + O_HNL);
    __nv_bfloat16* fh  = (__nv_bfloat16*)(base + O_FH);
    __nv_bfloat16* fl  = (__nv_bfloat16*)(base + O_FL);
    __nv_bfloat16* wTh = (__nv_bfloat16*)(base + O_WTH);
    __nv_bfloat16* wTl = (__nv_bfloat16*)(base + O_WTL);
    __nv_bfloat16* wsh = (__nv_bfloat16*)(base + O_WSH);
    __nv_bfloat16* wsl = (__nv_bfloat16*)(base + O_WSL);

    cudaFuncSetAttribute(gemm_bb<EP_Q, 0>,     cudaFuncAttributeMaxDynamicSharedMemorySize, GEMM_SMEM);
    cudaFuncSetAttribute(gemm_bb<EP_SC, 0>,    cudaFuncAttributeMaxDynamicSharedMemorySize, GEMM_SMEM);
    cudaFuncSetAttribute(gemm_bb<EP_HEAD, 1>,  cudaFuncAttributeMaxDynamicSharedMemorySize, GEMM_SMEM);
    cudaFuncSetAttribute(gemm_bb<EP_BIAS, 0>,  cudaFuncAttributeMaxDynamicSharedMemorySize, GEMM_SMEM);
    cudaFuncSetAttribute(gemm_bb<EP_SWISH, 0>, cudaFuncAttributeMaxDynamicSharedMemorySize, GEMM_SMEM);
    cudaFuncSetAttribute(gemm_bb<EP_OUT, 0>,   cudaFuncAttributeMaxDynamicSharedMemorySize, GEMM_SMEM);

    const long long sSD = (long long)SS * DD;   // 2,097,152
    const long long sSS = (long long)SS * SS;   // 4,194,304
    dim3 tb(32, 8);

    // wi^T split, Wsum^T split, x split
    tsplit<false><<<dim3(32, 32, 1), tb>>>(wi, wTh, wTl, DD, DD, 0, 0);
    tsplit<true><<<dim3(32, 32, 1), tb>>>(okern, wsh, wsl, DD, DD, 0, 0);
    split_ew<<<(BSR * DD) / 1024, 256>>>(x, xh, xl);

    // q = x @ wi  (fp32 + split)
    gemm_bb<EP_Q, 0><<<dim3(8, 32, 1), 256, GEMM_SMEM>>>(
        xh, xl, wTh, wTl, qf, qh, ql, nullptr, DD, DD, 0, 0, 0, 0, 0);

    // scores = (q @ q^T)/32, lower triangle only (136 tiles per batch)
    gemm_bb<EP_SC, 0><<<dim3(136, 1, 2), 256, GEMM_SMEM>>>(
        qh, ql, qh, ql, sc, nullptr, nullptr, nullptr,
        DD, SS, sSD, sSD, sSS, 0, 1);

    // causal softmax -> split probs (writes only cols < ceil((r+1)/128)*128)
    softmax_split<<<SB * SS, 256>>>(sc, Pph, Ppl);

    // head = q + P @ q  (trans-B: q read as [K,N], no transpose kernel)
    gemm_bb<EP_HEAD, 1><<<dim3(8, 16, 2), 256, GEMM_SMEM>>>(
        Pph, Ppl, qh, ql, nullptr, hdh, hdl, qf,
        SS, DD, sSS, sSD, sSD, sSD, 2);

    // h = head @ Wsum + bias  fp32
    gemm_bb<EP_BIAS, 0><<<dim3(8, 32, 1), 256, GEMM_SMEM>>>(
        hdh, hdl, wsh, wsl, hhf, nullptr, nullptr, obias,
        DD, DD, 0, 0, 0, 0, 0);

    // layernorm -> split
    ln_split<<<BSR, 256>>>(hhf, hnh, hnl);

    // f = swish(h @ wi)  (split out)
    gemm_bb<EP_SWISH, 0><<<dim3(8, 32, 1), 256, GEMM_SMEM>>>(
        hnh, hnl, wTh, wTl, nullptr, fh, fl, nullptr,
        DD, DD, 0, 0, 0, 0, 0);

    // out = f @ wi  fp32
    gemm_bb<EP_OUT, 0><<<dim3(8, 32, 1), 256, GEMM_SMEM>>>(
        fh, fl, wTh, wTl, out, nullptr, nullptr, nullptr,
        DD, DD, 0, 0, 0, 0, 0);
}

// round 7
// speedup vs baseline: 2.6138x; 1.0047x over previous
#include <cuda_runtime.h>
#include <cuda_bf16.h>
#include <stdint.h>
#include <math.h>

#define SB 2
#define SS 2048
#define DD 1024
#define BSR 4096
#define NEGV (-1e10f)
#define EPSV 1e-5f

// ---------------------------------------------------------------------------
// Scratch carve-out (one big device global; no allocation allowed)
// ---------------------------------------------------------------------------
__device__ __align__(256) unsigned char g_scratch[209715200ULL];  // 200 MB

#define O_QH   16777216ULL     // q hi bf16         [4096,1024]
#define O_QL   25165824ULL
#define O_XH   50331648ULL     // x split
#define O_XL   58720256ULL
#define O_SC   67108864ULL     // scores fp32       [2][2048][2048]
#define O_PH   100663296ULL    // softmax probs split
#define O_PL   117440512ULL
#define O_HDH  134217728ULL    // head split
#define O_HDL  142606336ULL
#define O_HHF  150994944ULL    // h fp32 (pre-LN)
#define O_HNH  167772160ULL    // h split (post-LN)
#define O_HNL  176160768ULL
#define O_FH   184549376ULL    // swish output split
#define O_FL   192937984ULL
#define O_WTH  201326592ULL    // wi^T split        [1024,1024]
#define O_WTL  203423744ULL
#define O_WSH  205520896ULL    // Wsum^T split
#define O_WSL  207618048ULL

// ---------------------------------------------------------------------------
// Portable sm_80+ primitives: cp.async, ldmatrix, bf16 mma.sync
// ---------------------------------------------------------------------------
__device__ __forceinline__ uint32_t smem_u32(const void* p) {
    uint32_t a;
    asm("{ .reg .u64 t; cvta.to.shared.u64 t, %1; cvt.u32.u64 %0, t; }"
        : "=r"(a) : "l"(p));
    return a;
}
__device__ __forceinline__ void cp16(uint32_t s, const void* g) {
    asm volatile("cp.async.cg.shared.global [%0], [%1], 16;" :: "r"(s), "l"(g));
}
#define CP_COMMIT() asm volatile("cp.async.commit_group;" ::: "memory")
template <int N> __device__ __forceinline__ void cp_wait() {
    asm volatile("cp.async.wait_group %0;" :: "n"(N) : "memory");
}
__device__ __forceinline__ void ldsm4(uint32_t (&r)[4], uint32_t a) {
    asm volatile("ldmatrix.sync.aligned.m8n8.x4.shared.b16 {%0,%1,%2,%3}, [%4];"
                 : "=r"(r[0]), "=r"(r[1]), "=r"(r[2]), "=r"(r[3]) : "r"(a));
}
__device__ __forceinline__ void ldsm4t(uint32_t (&r)[4], uint32_t a) {
    asm volatile("ldmatrix.sync.aligned.m8n8.x4.trans.shared.b16 {%0,%1,%2,%3}, [%4];"
                 : "=r"(r[0]), "=r"(r[1]), "=r"(r[2]), "=r"(r[3]) : "r"(a));
}
__device__ __forceinline__ void mma16816(float (&c)[4], const uint32_t (&a)[4],
                                         uint32_t b0, uint32_t b1) {
    asm volatile(
        "mma.sync.aligned.m16n8k16.row.col.f32.bf16.bf16.f32 "
        "{%0,%1,%2,%3}, {%4,%5,%6,%7}, {%8,%9}, {%0,%1,%2,%3};"
        : "+f"(c[0]), "+f"(c[1]), "+f"(c[2]), "+f"(c[3])
        : "r"(a[0]), "r"(a[1]), "r"(a[2]), "r"(a[3]), "r"(b0), "r"(b1));
}

__device__ __forceinline__ void split_f(float v, __nv_bfloat16& h, __nv_bfloat16& l) {
    h = __float2bfloat16(v);
    l = __float2bfloat16(v - __bfloat162float(h));
}

// ---------------------------------------------------------------------------
// GEMM: C[M,N] = A[M,K] @ B^T, pre-split bf16 hi/lo, mma.sync HMMA.
// B layout: TRB=0 -> B stored [N,K]. TRB=1 -> B stored [K,N] (ldmatrix.trans).
// CTA tile 128x128, 8 warps (2m x 4n of 64x32), K-chunk 32, 2-stage, 2 CTA/SM.
// MMA order: three term-sweeps (16 independent MMAs between RAW deps on acc).
// ---------------------------------------------------------------------------
enum { EP_Q = 0, EP_SC = 1, EP_HEAD = 2, EP_BIAS = 3, EP_SWISH = 4, EP_OUT = 5 };

#define RPAD 40
#define MATB (128 * RPAD * 2)       // 10240 bytes: A tiles + non-trans B tiles
#define BTROW 272                   // trans-B row bytes: 128 bf16 + 8 pad
#define BTMATB (32 * BTROW)         // 8704 bytes per trans-B matrix
#define OFF_AH 0
#define OFF_AL (MATB)
#define OFF_BH (2 * MATB)
#define GEMM_SMEM 81920

template <int EPI, int TRB>
__global__ __launch_bounds__(256, 2) void gemm_bb(
    const __nv_bfloat16* __restrict__ Agh, const __nv_bfloat16* __restrict__ Agl,
    const __nv_bfloat16* __restrict__ Bgh, const __nv_bfloat16* __restrict__ Bgl,
    float* __restrict__ Cf, __nv_bfloat16* __restrict__ Ch,
    __nv_bfloat16* __restrict__ Cl, const float* __restrict__ E,
    int K, int N, long long sA, long long sB, long long sC, long long sE,
    int causal)
{
    extern __shared__ unsigned char smb[];
    constexpr int BMATB = TRB ? BTMATB : MATB;
    constexpr int STAGEB = 2 * MATB + 2 * BMATB;

    const int tid = threadIdx.x;
    const int wid = tid >> 5;
    const int lane = tid & 31;
    const int z = blockIdx.z;

    int bi = blockIdx.y, bj = blockIdx.x;
    if (EPI == EP_SC) {
        // triangular decode: blockIdx.x in [0,136) -> (bi >= bj)
        int xx = blockIdx.x;
        bi = (int)((sqrtf(8.0f * xx + 1.0f) - 1.0f) * 0.5f);
        while ((bi + 1) * (bi + 2) / 2 <= xx) bi++;
        while (bi * (bi + 1) / 2 > xx) bi--;
        bj = xx - bi * (bi + 1) / 2;
    }
    const int row0 = bi * 128;
    const int col0 = bj * 128;
    const bool diag = (EPI == EP_SC) && (col0 == row0);

    const __nv_bfloat16* Ah = Agh + (long long)z * sA;
    const __nv_bfloat16* Al = Agl + (long long)z * sA;
    const __nv_bfloat16* Bh = Bgh + (long long)z * sB;
    const __nv_bfloat16* Bl = Bgl + (long long)z * sB;

    const int kEnd = (causal == 2) ? min(K, row0 + 128) : K;
    const int nch = kEnd >> 5;

    const uint32_t sbase = smem_u32(smb);

    // ---- A loader: thread -> row tid>>1, two 16B quads (tid&1)*2+{0,1}
    const int ldr = tid >> 1;
    const int ldq = (tid & 1) * 2;
    const size_t aRow = (size_t)(row0 + ldr) * K;
    const size_t bRow = (size_t)(col0 + ldr) * K;     // non-trans only
    const uint32_t sRow = (uint32_t)(ldr * (RPAD * 2));

    // ---- warp tile ----
    const int m0 = (wid >> 2) * 64;
    const int n0 = (wid & 3) * 32;
    // diag tile: warps entirely above the diagonal have no live outputs
    const bool wskip = diag && (n0 > m0 + 63);

    uint32_t aoff[4];
#pragma unroll
    for (int mt = 0; mt < 4; mt++)
        aoff[mt] = (uint32_t)((m0 + mt * 16 + (lane & 15)) * (RPAD * 2) +
                              ((lane >> 4) * 8) * 2);
    // B ldmatrix offsets
    uint32_t boff[2];
    if (!TRB) {
#pragma unroll
        for (int p = 0; p < 2; p++)
            boff[p] = (uint32_t)((n0 + p * 16 + ((lane >> 4) << 3) + (lane & 7)) *
                                     (RPAD * 2) +
                                 (((lane >> 3) & 1) * 8) * 2);
    } else {
        // trans: lane -> k-row and n-col of the [K=32, N=128] tile
        const int kr = ((lane >> 3) & 1) * 8 + (lane & 7);
#pragma unroll
        for (int p = 0; p < 2; p++) {
            const int nc = n0 + p * 16 + (lane >> 4) * 8;
            boff[p] = (uint32_t)(kr * BTROW + nc * 2);
        }
    }

    float acc[4][4][4] = {};

#define ISSUE(c, st) { \
    const int kk = (c) * 32; \
    const uint32_t sb = sbase + (st) * STAGEB; \
    _Pragma("unroll") for (int u = 0; u < 2; u++) { \
        const int q = ldq + u; \
        cp16(sb + OFF_AH + sRow + q * 16, Ah + aRow + kk + q * 8); \
        cp16(sb + OFF_AL + sRow + q * 16, Al + aRow + kk + q * 8); \
        if (!TRB) { \
            cp16(sb + OFF_BH + sRow + q * 16, Bh + bRow + kk + q * 8); \
            cp16(sb + OFF_BH + BMATB + sRow + q * 16, Bl + bRow + kk + q * 8); \
        } else { \
            const int qi = tid * 2 + u; \
            const int brr = qi >> 4, bqc = qi & 15; \
            const size_t g = (size_t)(kk + brr) * N + col0 + bqc * 8; \
            const uint32_t s = OFF_BH + (uint32_t)(brr * BTROW + bqc * 16); \
            cp16(sb + s, Bh + g); \
            cp16(sb + BMATB + s, Bl + g); \
        } \
    } }

    ISSUE(0, 0);
    CP_COMMIT();

    for (int c = 0; c < nch; c++) {
        cp_wait<0>();
        __syncthreads();
        // Safe stage reuse: the barrier proves all warps finished reading the
        // stage this issue overwrites.
        if (c + 1 < nch) { ISSUE(c + 1, (c + 1) & 1); }
        CP_COMMIT();

        const uint32_t stb = sbase + (c & 1) * STAGEB;
        if (!wskip) {
#pragma unroll
            for (int ks = 0; ks < 2; ks++) {
                const uint32_t ksoA = (uint32_t)(ks * 32);
                const uint32_t ksoB = TRB ? (uint32_t)(ks * 16 * BTROW)
                                          : (uint32_t)(ks * 32);
                uint32_t ahf[4][4], alf[4][4], bhf[2][4], blf[2][4];
#pragma unroll
                for (int mt = 0; mt < 4; mt++) {
                    ldsm4(ahf[mt], stb + OFF_AH + aoff[mt] + ksoA);
                    ldsm4(alf[mt], stb + OFF_AL + aoff[mt] + ksoA);
                }
#pragma unroll
                for (int p = 0; p < 2; p++) {
                    if (!TRB) {
                        ldsm4(bhf[p], stb + OFF_BH + boff[p] + ksoB);
                        ldsm4(blf[p], stb + OFF_BH + BMATB + boff[p] + ksoB);
                    } else {
                        ldsm4t(bhf[p], stb + OFF_BH + boff[p] + ksoB);
                        ldsm4t(blf[p], stb + OFF_BH + BMATB + boff[p] + ksoB);
                    }
                }
                // Term sweeps: 16 independent MMAs between writes to same acc.
#pragma unroll
                for (int mt = 0; mt < 4; mt++)
#pragma unroll
                    for (int nt = 0; nt < 4; nt++) {
                        const int p = nt >> 1, h = (nt & 1) * 2;
                        mma16816(acc[mt][nt], ahf[mt], bhf[p][h], bhf[p][h + 1]);
                    }
#pragma unroll
                for (int mt = 0; mt < 4; mt++)
#pragma unroll
                    for (int nt = 0; nt < 4; nt++) {
                        const int p = nt >> 1, h = (nt & 1) * 2;
                        mma16816(acc[mt][nt], alf[mt], bhf[p][h], bhf[p][h + 1]);
                    }
#pragma unroll
                for (int mt = 0; mt < 4; mt++)
#pragma unroll
                    for (int nt = 0; nt < 4; nt++) {
                        const int p = nt >> 1, h = (nt & 1) * 2;
                        mma16816(acc[mt][nt], ahf[mt], blf[p][h], blf[p][h + 1]);
                    }
            }
        }
        __syncthreads();
    }
#undef ISSUE

    // ------------------- epilogue -------------------
    float* Cfz = (EPI == EP_SC || EPI == EP_BIAS || EPI == EP_OUT)
                     ? Cf + (long long)z * sC : nullptr;
    __nv_bfloat16* Chz = (EPI == EP_Q || EPI == EP_HEAD || EPI == EP_SWISH)
                             ? Ch + (long long)z * sC : nullptr;
    __nv_bfloat16* Clz = (EPI == EP_Q || EPI == EP_HEAD || EPI == EP_SWISH)
                             ? Cl + (long long)z * sC : nullptr;

#pragma unroll
    for (int mt = 0; mt < 4; mt++) {
#pragma unroll
        for (int nt = 0; nt < 4; nt++) {
#pragma unroll
            for (int half = 0; half < 2; half++) {
                const int r = row0 + m0 + mt * 16 + (lane >> 2) + half * 8;
                const int cc = col0 + n0 + nt * 8 + (lane & 3) * 2;
                float v0 = acc[mt][nt][half * 2];
                float v1 = acc[mt][nt][half * 2 + 1];

                if (EPI == EP_SC) {
                    // skip stores entirely above the diagonal (never read)
                    if (!diag || cc <= r) {
                        v0 *= 0.03125f; v1 *= 0.03125f;
                        *reinterpret_cast<float2*>(&Cfz[(long long)r * N + cc]) =
                            make_float2(v0, v1);
                    }
                } else if (EPI == EP_BIAS) {
                    float2 bb = *reinterpret_cast<const float2*>(&E[cc]);
                    *reinterpret_cast<float2*>(&Cfz[(long long)r * N + cc]) =
                        make_float2(v0 + bb.x, v1 + bb.y);
                } else if (EPI == EP_OUT) {
                    *reinterpret_cast<float2*>(&Cfz[(long long)r * N + cc]) =
                        make_float2(v0, v1);
                } else {
                    if (EPI == EP_HEAD) {
                        // residual q = qh + ql (B operand IS q in [K=S, N=D])
                        __nv_bfloat162 eh = *reinterpret_cast<const __nv_bfloat162*>(
                            &Bh[(long long)r * N + cc]);
                        __nv_bfloat162 el = *reinterpret_cast<const __nv_bfloat162*>(
                            &Bl[(long long)r * N + cc]);
                        v0 += __bfloat162float(eh.x) + __bfloat162float(el.x);
                        v1 += __bfloat162float(eh.y) + __bfloat162float(el.y);
                    }
                    if (EPI == EP_SWISH) {
                        v0 = v0 / (1.0f + expf(-v0));
                        v1 = v1 / (1.0f + expf(-v1));
                    }
                    __nv_bfloat16 h0, h1, l0, l1;
                    split_f(v0, h0, l0);
                    split_f(v1, h1, l1);
                    *reinterpret_cast<__nv_bfloat162*>(&Chz[(long long)r * N + cc]) =
                        __halves2bfloat162(h0, h1);
                    *reinterpret_cast<__nv_bfloat162*>(&Clz[(long long)r * N + cc]) =
                        __halves2bfloat162(l0, l1);
                }
            }
        }
    }
}

// ---------------------------------------------------------------------------
// Transpose + split: dst[c][r] = split(src[r][c]); optional sum over 8 heads
// ---------------------------------------------------------------------------
template <bool SUMH>
__global__ void tsplit(const float* __restrict__ S, __nv_bfloat16* __restrict__ Dh,
                       __nv_bfloat16* __restrict__ Dl, int R, int C,
                       long long sS, long long sD)
{
    __shared__ float t[32][33];
    const int tx = threadIdx.x, ty = threadIdx.y;
    const int c0 = blockIdx.x * 32, r0 = blockIdx.y * 32, z = blockIdx.z;
    const float* Sz = S + (long long)z * sS;
#pragma unroll
    for (int i = 0; i < 4; i++) {
        int r = r0 + ty + i * 8;
        float v;
        if (SUMH) {
            v = 0.f;
#pragma unroll
            for (int h = 0; h < 8; h++)
                v += S[(size_t)(h * 1024 + r) * C + c0 + tx];
        } else {
            v = Sz[(size_t)r * C + c0 + tx];
        }
        t[ty + i * 8][tx] = v;
    }
    __syncthreads();
#pragma unroll
    for (int i = 0; i < 4; i++) {
        int orow = c0 + ty + i * 8;
        float v = t[tx][ty + i * 8];
        __nv_bfloat16 h, l;
        split_f(v, h, l);
        Dh[(long long)z * sD + (size_t)orow * R + r0 + tx] = h;
        Dl[(long long)z * sD + (size_t)orow * R + r0 + tx] = l;
    }
}

// ---------------------------------------------------------------------------
// Elementwise split
// ---------------------------------------------------------------------------
__global__ void split_ew(const float* __restrict__ X, __nv_bfloat16* __restrict__ H,
                         __nv_bfloat16* __restrict__ L)
{
    size_t i = ((size_t)blockIdx.x * 256 + threadIdx.x);
    float4 v = reinterpret_cast<const float4*>(X)[i];
    __nv_bfloat16 h0, h1, h2, h3, l0, l1, l2, l3;
    split_f(v.x, h0, l0); split_f(v.y, h1, l1);
    split_f(v.z, h2, l2); split_f(v.w, h3, l3);
    reinterpret_cast<__nv_bfloat162*>(H)[i * 2]     = __halves2bfloat162(h0, h1);
    reinterpret_cast<__nv_bfloat162*>(H)[i * 2 + 1] = __halves2bfloat162(h2, h3);
    reinterpret_cast<__nv_bfloat162*>(L)[i * 2]     = __halves2bfloat162(l0, l1);
    reinterpret_cast<__nv_bfloat162*>(L)[i * 2 + 1] = __halves2bfloat162(l2, l3);
}

// ---------------------------------------------------------------------------
// Reductions
// ---------------------------------------------------------------------------
__device__ __forceinline__ float warpMax(float v) {
#pragma unroll
    for (int o = 16; o; o >>= 1) v = fmaxf(v, __shfl_xor_sync(0xffffffffu, v, o));
    return v;
}
__device__ __forceinline__ float warpSum(float v) {
#pragma unroll
    for (int o = 16; o; o >>= 1) v += __shfl_xor_sync(0xffffffffu, v, o);
    return v;
}

// Causal softmax over scores rows; writes split probs only for the K range
// the PV GEMM reads (cols < kLim = ceil((r+1)/128)*128). One block per row.
__global__ __launch_bounds__(256) void softmax_split(
    const float* __restrict__ Sc, __nv_bfloat16* __restrict__ Ph,
    __nv_bfloat16* __restrict__ Pl)
{
    const int r = blockIdx.x & (SS - 1);
    const int kLim = ((r >> 7) + 1) << 7;
    const float* row = Sc + (long long)blockIdx.x * SS;
    __nv_bfloat16* oh = Ph + (long long)blockIdx.x * SS;
    __nv_bfloat16* ol = Pl + (long long)blockIdx.x * SS;
    const int tid = threadIdx.x, lane = tid & 31, w = tid >> 5;
    __shared__ float red[32];

    const int c0 = tid * 4;
    const int c1 = 1024 + tid * 4;
    float4 v0 = make_float4(NEGV, NEGV, NEGV, NEGV);
    float4 v1 = make_float4(NEGV, NEGV, NEGV, NEGV);
    if (c0 < kLim) v0 = reinterpret_cast<const float4*>(row)[tid];
    if (c1 < kLim) v1 = reinterpret_cast<const float4*>(row)[tid + 256];

    float m = -3.4e38f;
    if (c0 + 0 <= r) m = fmaxf(m, v0.x);
    if (c0 + 1 <= r) m = fmaxf(m, v0.y);
    if (c0 + 2 <= r) m = fmaxf(m, v0.z);
    if (c0 + 3 <= r) m = fmaxf(m, v0.w);
    if (c1 + 0 <= r) m = fmaxf(m, v1.x);
    if (c1 + 1 <= r) m = fmaxf(m, v1.y);
    if (c1 + 2 <= r) m = fmaxf(m, v1.z);
    if (c1 + 3 <= r) m = fmaxf(m, v1.w);
    m = warpMax(m);
    if (lane == 0) red[w] = m;
    __syncthreads();
    if (tid < 32) { float x = (tid < 8) ? red[tid] : -3.4e38f; x = warpMax(x);
                    if (tid == 0) red[0] = x; }
    __syncthreads();
    m = red[0];
    __syncthreads();

    float e[8];
    e[0] = (c0 + 0 <= r) ? expf(v0.x - m) : 0.f;
    e[1] = (c0 + 1 <= r) ? expf(v0.y - m) : 0.f;
    e[2] = (c0 + 2 <= r) ? expf(v0.z - m) : 0.f;
    e[3] = (c0 + 3 <= r) ? expf(v0.w - m) : 0.f;
    e[4] = (c1 + 0 <= r) ? expf(v1.x - m) : 0.f;
    e[5] = (c1 + 1 <= r) ? expf(v1.y - m) : 0.f;
    e[6] = (c1 + 2 <= r) ? expf(v1.z - m) : 0.f;
    e[7] = (c1 + 3 <= r) ? expf(v1.w - m) : 0.f;
    float s = e[0] + e[1] + e[2] + e[3] + e[4] + e[5] + e[6] + e[7];
    s = warpSum(s);
    if (lane == 0) red[w] = s;
    __syncthreads();
    if (tid < 32) { float x = (tid < 8) ? red[tid] : 0.f; x = warpSum(x);
                    if (tid == 0) red[0] = x; }
    __syncthreads();
    const float inv = 1.0f / red[0];

    __nv_bfloat16 h[8], l[8];
#pragma unroll
    for (int u = 0; u < 8; u++) split_f(e[u] * inv, h[u], l[u]);
    __nv_bfloat162* phh = reinterpret_cast<__nv_bfloat162*>(oh);
    __nv_bfloat162* pll = reinterpret_cast<__nv_bfloat162*>(ol);
    if (c0 < kLim) {
        phh[tid * 2]     = __halves2bfloat162(h[0], h[1]);
        phh[tid * 2 + 1] = __halves2bfloat162(h[2], h[3]);
        pll[tid * 2]     = __halves2bfloat162(l[0], l[1]);
        pll[tid * 2 + 1] = __halves2bfloat162(l[2], l[3]);
    }
    if (c1 < kLim) {
        phh[(tid + 256) * 2]     = __halves2bfloat162(h[4], h[5]);
        phh[(tid + 256) * 2 + 1] = __halves2bfloat162(h[6], h[7]);
        pll[(tid + 256) * 2]     = __halves2bfloat162(l[4], l[5]);
        pll[(tid + 256) * 2 + 1] = __halves2bfloat162(l[6], l[7]);
    }
}

// LayerNorm -> split. One block per row (1024 cols).
__global__ __launch_bounds__(256) void ln_split(
    const float* __restrict__ Hf, __nv_bfloat16* __restrict__ Oh,
    __nv_bfloat16* __restrict__ Ol)
{
    const float* row = Hf + (long long)blockIdx.x * DD;
    __nv_bfloat16* oh = Oh + (long long)blockIdx.x * DD;
    __nv_bfloat16* ol = Ol + (long long)blockIdx.x * DD;
    const int tid = threadIdx.x, lane = tid & 31, w = tid >> 5;
    __shared__ float r1[32], r2[32];

    float4 v = reinterpret_cast<const float4*>(row)[tid];
    float s = v.x + v.y + v.z + v.w;
    float s2 = v.x * v.x + v.y * v.y + v.z * v.z + v.w * v.w;
    s = warpSum(s); s2 = warpSum(s2);
    if (lane == 0) { r1[w] = s; r2[w] = s2; }
    __syncthreads();
    if (tid < 32) {
        float a = (tid < 8) ? r1[tid] : 0.f;
        float b = (tid < 8) ? r2[tid] : 0.f;
        a = warpSum(a); b = warpSum(b);
        if (tid == 0) { r1[0] = a; r2[0] = b; }
    }
    __syncthreads();
    const float mean = r1[0] * (1.0f / DD);
    const float msq = r2[0] * (1.0f / DD);
    const float inv = rsqrtf(msq - mean * mean + EPSV);

    float y[4] = {(v.x - mean) * inv, (v.y - mean) * inv,
                  (v.z - mean) * inv, (v.w - mean) * inv};
    __nv_bfloat16 h[4], l[4];
#pragma unroll
    for (int u = 0; u < 4; u++) split_f(y[u], h[u], l[u]);
    reinterpret_cast<__nv_bfloat162*>(oh)[tid * 2]     = __halves2bfloat162(h[0], h[1]);
    reinterpret_cast<__nv_bfloat162*>(oh)[tid * 2 + 1] = __halves2bfloat162(h[2], h[3]);
    reinterpret_cast<__nv_bfloat162*>(ol)[tid * 2]     = __halves2bfloat162(l[0], l[1]);
    reinterpret_cast<__nv_bfloat162*>(ol)[tid * 2 + 1] = __halves2bfloat162(l[2], l[3]);
}

// ---------------------------------------------------------------------------
// Launch
// ---------------------------------------------------------------------------
extern "C" void kernel_launch(void* const* d_in, const int* in_sizes, int n_in,
                              void* d_out, int out_size)
{
    (void)in_sizes; (void)n_in; (void)out_size;
    const float* x     = (const float*)d_in[0];
    const float* wi    = (const float*)d_in[2];
    const float* okern = (const float*)d_in[3];
    const float* obias = (const float*)d_in[4];
    float* out = (float*)d_out;

    unsigned char* base;
    cudaGetSymbolAddress((void**)&base, g_scratch);
    float* sc  = (float*)(base + O_SC);
    float* hhf = (float*)(base + O_HHF);
    __nv_bfloat16* qh  = (__nv_bfloat16*)(base + O_QH);
    __nv_bfloat16* ql  = (__nv_bfloat16*)(base + O_QL);
    __nv_bfloat16* xh  = (__nv_bfloat16*)(base + O_XH);
    __nv_bfloat16* xl  = (__nv_bfloat16*)(base + O_XL);
    __nv_bfloat16* Pph = (__nv_bfloat16*)(base + O_PH);
    __nv_bfloat16* Ppl = (__nv_bfloat16*)(base + O_PL);
    __nv_bfloat16* hdh = (__nv_bfloat16*)(base + O_HDH);
    __nv_bfloat16* hdl = (__nv_bfloat16*)(base + O_HDL);
    __nv_bfloat16* hnh = (__nv_bfloat16*)(base + O_HNH);
    __nv_bfloat16* hnl = (__nv_bfloat16*)(base + O_HNL);
    __nv_bfloat16* fh  = (__nv_bfloat16*)(base + O_FH);
    __nv_bfloat16* fl  = (__nv_bfloat16*)(base + O_FL);
    __nv_bfloat16* wTh = (__nv_bfloat16*)(base + O_WTH);
    __nv_bfloat16* wTl = (__nv_bfloat16*)(base + O_WTL);
    __nv_bfloat16* wsh = (__nv_bfloat16*)(base + O_WSH);
    __nv_bfloat16* wsl = (__nv_bfloat16*)(base + O_WSL);

    cudaFuncSetAttribute(gemm_bb<EP_Q, 0>,     cudaFuncAttributeMaxDynamicSharedMemorySize, GEMM_SMEM);
    cudaFuncSetAttribute(gemm_bb<EP_SC, 0>,    cudaFuncAttributeMaxDynamicSharedMemorySize, GEMM_SMEM);
    cudaFuncSetAttribute(gemm_bb<EP_HEAD, 1>,  cudaFuncAttributeMaxDynamicSharedMemorySize, GEMM_SMEM);
    cudaFuncSetAttribute(gemm_bb<EP_BIAS, 0>,  cudaFuncAttributeMaxDynamicSharedMemorySize, GEMM_SMEM);
    cudaFuncSetAttribute(gemm_bb<EP_SWISH, 0>, cudaFuncAttributeMaxDynamicSharedMemorySize, GEMM_SMEM);
    cudaFuncSetAttribute(gemm_bb<EP_OUT, 0>,   cudaFuncAttributeMaxDynamicSharedMemorySize, GEMM_SMEM);

    const long long sSD = (long long)SS * DD;   // 2,097,152
    const long long sSS = (long long)SS * SS;   // 4,194,304
    dim3 tb(32, 8);

    // wi^T split, Wsum^T split, x split
    tsplit<false><<<dim3(32, 32, 1), tb>>>(wi, wTh, wTl, DD, DD, 0, 0);
    tsplit<true><<<dim3(32, 32, 1), tb>>>(okern, wsh, wsl, DD, DD, 0, 0);
    split_ew<<<(BSR * DD) / 1024, 256>>>(x, xh, xl);

    // q = x @ wi  (split out only; residual later reconstructed as qh+ql)
    gemm_bb<EP_Q, 0><<<dim3(8, 32, 1), 256, GEMM_SMEM>>>(
        xh, xl, wTh, wTl, nullptr, qh, ql, nullptr, DD, DD, 0, 0, 0, 0, 0);

    // scores = (q @ q^T)/32, lower triangle only (136 tiles per batch)
    gemm_bb<EP_SC, 0><<<dim3(136, 1, 2), 256, GEMM_SMEM>>>(
        qh, ql, qh, ql, sc, nullptr, nullptr, nullptr,
        DD, SS, sSD, sSD, sSS, 0, 1);

    // causal softmax -> split probs (writes only cols < ceil((r+1)/128)*128)
    softmax_split<<<SB * SS, 256>>>(sc, Pph, Ppl);

    // head = q + P @ q  (trans-B: q read as [K,N]; residual from qh+ql)
    gemm_bb<EP_HEAD, 1><<<dim3(8, 16, 2), 256, GEMM_SMEM>>>(
        Pph, Ppl, qh, ql, nullptr, hdh, hdl, nullptr,
        SS, DD, sSS, sSD, sSD, sSD, 2);

    // h = head @ Wsum + bias  fp32
    gemm_bb<EP_BIAS, 0><<<dim3(8, 32, 1), 256, GEMM_SMEM>>>(
        hdh, hdl, wsh, wsl, hhf, nullptr, nullptr, obias,
        DD, DD, 0, 0, 0, 0, 0);

    // layernorm -> split
    ln_split<<<BSR, 256>>>(hhf, hnh, hnl);

    // f = swish(h @ wi)  (split out)
    gemm_bb<EP_SWISH, 0><<<dim3(8, 32, 1), 256, GEMM_SMEM>>>(
        hnh, hnl, wTh, wTl, nullptr, fh, fl, nullptr,
        DD, DD, 0, 0, 0, 0, 0);

    // out = f @ wi  fp32
    gemm_bb<EP_OUT, 0><<<dim3(8, 32, 1), 256, GEMM_SMEM>>>(
        fh, fl, wTh, wTl, out, nullptr, nullptr, nullptr,
        DD, DD, 0, 0, 0, 0, 0);
}

// round 8
// speedup vs baseline: 3.5117x; 1.3435x over previous
#include <cuda_runtime.h>
#include <cuda_fp16.h>
#include <stdint.h>
#include <math.h>

#define SB 2
#define SS 2048
#define DD 1024
#define BSR 4096
#define NEGV (-1e10f)
#define EPSV 1e-5f

// ---------------------------------------------------------------------------
// Scratch carve-out (one big device global; no allocation allowed)
// ---------------------------------------------------------------------------
__device__ __align__(256) unsigned char g_scratch[209715200ULL];  // 200 MB

#define O_QH   16777216ULL     // q hi fp16         [4096,1024]
#define O_QL   25165824ULL     // q lo fp16
#define O_XH   50331648ULL     // x split
#define O_XL   58720256ULL
#define O_SC   67108864ULL     // scores fp32       [2][2048][2048]
#define O_PH   100663296ULL    // softmax probs split
#define O_PL   117440512ULL
#define O_HDH  134217728ULL    // head split
#define O_HDL  142606336ULL
#define O_HHF  150994944ULL    // h fp32 (pre-LN)
#define O_HNH  167772160ULL    // h split (post-LN)
#define O_HNL  176160768ULL
#define O_FH   184549376ULL    // swish output split
#define O_FL   192937984ULL
#define O_WT   201326592ULL    // wi^T single fp16  [1024,1024]
#define O_WS   205520896ULL    // Wsum^T single fp16

// ---------------------------------------------------------------------------
// Portable sm_80+ primitives: cp.async, ldmatrix, fp16 mma.sync
// ---------------------------------------------------------------------------
__device__ __forceinline__ uint32_t smem_u32(const void* p) {
    uint32_t a;
    asm("{ .reg .u64 t; cvta.to.shared.u64 t, %1; cvt.u32.u64 %0, t; }"
        : "=r"(a) : "l"(p));
    return a;
}
__device__ __forceinline__ void cp16(uint32_t s, const void* g) {
    asm volatile("cp.async.cg.shared.global [%0], [%1], 16;" :: "r"(s), "l"(g));
}
#define CP_COMMIT() asm volatile("cp.async.commit_group;" ::: "memory")
template <int N> __device__ __forceinline__ void cp_wait() {
    asm volatile("cp.async.wait_group %0;" :: "n"(N) : "memory");
}
__device__ __forceinline__ void ldsm4(uint32_t (&r)[4], uint32_t a) {
    asm volatile("ldmatrix.sync.aligned.m8n8.x4.shared.b16 {%0,%1,%2,%3}, [%4];"
                 : "=r"(r[0]), "=r"(r[1]), "=r"(r[2]), "=r"(r[3]) : "r"(a));
}
__device__ __forceinline__ void ldsm4t(uint32_t (&r)[4], uint32_t a) {
    asm volatile("ldmatrix.sync.aligned.m8n8.x4.trans.shared.b16 {%0,%1,%2,%3}, [%4];"
                 : "=r"(r[0]), "=r"(r[1]), "=r"(r[2]), "=r"(r[3]) : "r"(a));
}
__device__ __forceinline__ void mma16816(float (&c)[4], const uint32_t (&a)[4],
                                         uint32_t b0, uint32_t b1) {
    asm volatile(
        "mma.sync.aligned.m16n8k16.row.col.f32.f16.f16.f32 "
        "{%0,%1,%2,%3}, {%4,%5,%6,%7}, {%8,%9}, {%0,%1,%2,%3};"
        : "+f"(c[0]), "+f"(c[1]), "+f"(c[2]), "+f"(c[3])
        : "r"(a[0]), "r"(a[1]), "r"(a[2]), "r"(a[3]), "r"(b0), "r"(b1));
}

__device__ __forceinline__ void split_h(float v, __half& h, __half& l) {
    h = __float2half(v);
    l = __float2half(v - __half2float(h));
}

// ---------------------------------------------------------------------------
// GEMM: C[M,N] = A[M,K] @ B^T. A pre-split fp16 hi/lo (2 terms), B single fp16.
// Products: Ah*B + Al*B (A exact to 2^-23; B error 2^-12 -> ~2e-4 rel).
// B layout: TRB=0 -> B stored [N,K]. TRB=1 -> B stored [K,N] (ldmatrix.trans).
// CTA tile 128x128, 8 warps (2m x 4n of 64x32), K-chunk 32, 2-stage, 2 CTA/SM.
// ---------------------------------------------------------------------------
enum { EP_Q = 0, EP_SC = 1, EP_HEAD = 2, EP_BIAS = 3, EP_SWISH = 4, EP_OUT = 5 };

#define RPAD 40
#define MATB (128 * RPAD * 2)       // 10240 bytes: A tiles + non-trans B tile
#define BTROW 272                   // trans-B row bytes: 128 fp16 + 8 pad
#define BTMATB (32 * BTROW)         // 8704 bytes trans-B tile
#define OFF_AH 0
#define OFF_AL (MATB)
#define OFF_B  (2 * MATB)
#define GEMM_SMEM 65536

template <int EPI, int TRB>
__global__ __launch_bounds__(256, 2) void gemm_hh(
    const __half* __restrict__ Agh, const __half* __restrict__ Agl,
    const __half* __restrict__ Bg, const __half* __restrict__ Bgl,
    float* __restrict__ Cf, __half* __restrict__ Ch,
    __half* __restrict__ Cl, const float* __restrict__ E,
    int K, int N, long long sA, long long sB, long long sC, long long sE,
    int causal)
{
    extern __shared__ unsigned char smb[];
    constexpr int BMATB = TRB ? BTMATB : MATB;
    constexpr int STAGEB = 2 * MATB + BMATB;

    const int tid = threadIdx.x;
    const int wid = tid >> 5;
    const int lane = tid & 31;
    const int z = blockIdx.z;

    int bi = blockIdx.y, bj = blockIdx.x;
    if (EPI == EP_SC) {
        int xx = blockIdx.x;
        bi = (int)((sqrtf(8.0f * xx + 1.0f) - 1.0f) * 0.5f);
        while ((bi + 1) * (bi + 2) / 2 <= xx) bi++;
        while (bi * (bi + 1) / 2 > xx) bi--;
        bj = xx - bi * (bi + 1) / 2;
    }
    const int row0 = bi * 128;
    const int col0 = bj * 128;
    const bool diag = (EPI == EP_SC) && (col0 == row0);

    const __half* Ah = Agh + (long long)z * sA;
    const __half* Al = Agl + (long long)z * sA;
    const __half* Bm = Bg + (long long)z * sB;
    const __half* Bl = (EPI == EP_HEAD) ? Bgl + (long long)z * sB : nullptr;

    const int kEnd = (causal == 2) ? min(K, row0 + 128) : K;
    const int nch = kEnd >> 5;

    const uint32_t sbase = smem_u32(smb);

    const int ldr = tid >> 1;
    const int ldq = (tid & 1) * 2;
    const size_t aRow = (size_t)(row0 + ldr) * K;
    const size_t bRow = (size_t)(col0 + ldr) * K;     // non-trans only
    const uint32_t sRow = (uint32_t)(ldr * (RPAD * 2));

    const int m0 = (wid >> 2) * 64;
    const int n0 = (wid & 3) * 32;
    const bool wskip = diag && (n0 > m0 + 63);

    uint32_t aoff[4];
#pragma unroll
    for (int mt = 0; mt < 4; mt++)
        aoff[mt] = (uint32_t)((m0 + mt * 16 + (lane & 15)) * (RPAD * 2) +
                              ((lane >> 4) * 8) * 2);
    uint32_t boff[2];
    if (!TRB) {
#pragma unroll
        for (int p = 0; p < 2; p++)
            boff[p] = (uint32_t)((n0 + p * 16 + ((lane >> 4) << 3) + (lane & 7)) *
                                     (RPAD * 2) +
                                 (((lane >> 3) & 1) * 8) * 2);
    } else {
        const int kr = ((lane >> 3) & 1) * 8 + (lane & 7);
#pragma unroll
        for (int p = 0; p < 2; p++) {
            const int nc = n0 + p * 16 + (lane >> 4) * 8;
            boff[p] = (uint32_t)(kr * BTROW + nc * 2);
        }
    }

    float acc[4][4][4] = {};

#define ISSUE(c, st) { \
    const int kk = (c) * 32; \
    const uint32_t sb = sbase + (st) * STAGEB; \
    _Pragma("unroll") for (int u = 0; u < 2; u++) { \
        const int q = ldq + u; \
        cp16(sb + OFF_AH + sRow + q * 16, Ah + aRow + kk + q * 8); \
        cp16(sb + OFF_AL + sRow + q * 16, Al + aRow + kk + q * 8); \
        if (!TRB) { \
            cp16(sb + OFF_B + sRow + q * 16, Bm + bRow + kk + q * 8); \
        } else { \
            const int qi = tid * 2 + u; \
            const int brr = qi >> 4, bqc = qi & 15; \
            const size_t g = (size_t)(kk + brr) * N + col0 + bqc * 8; \
            cp16(sb + OFF_B + (uint32_t)(brr * BTROW + bqc * 16), Bm + g); \
        } \
    } }

    ISSUE(0, 0);
    CP_COMMIT();

    for (int c = 0; c < nch; c++) {
        cp_wait<0>();
        __syncthreads();
        if (c + 1 < nch) { ISSUE(c + 1, (c + 1) & 1); }
        CP_COMMIT();

        const uint32_t stb = sbase + (c & 1) * STAGEB;
        if (!wskip) {
#pragma unroll
            for (int ks = 0; ks < 2; ks++) {
                const uint32_t ksoA = (uint32_t)(ks * 32);
                const uint32_t ksoB = TRB ? (uint32_t)(ks * 16 * BTROW)
                                          : (uint32_t)(ks * 32);
                uint32_t ahf[4][4], alf[4][4], bf[2][4];
#pragma unroll
                for (int mt = 0; mt < 4; mt++) {
                    ldsm4(ahf[mt], stb + OFF_AH + aoff[mt] + ksoA);
                    ldsm4(alf[mt], stb + OFF_AL + aoff[mt] + ksoA);
                }
#pragma unroll
                for (int p = 0; p < 2; p++) {
                    if (!TRB) ldsm4(bf[p], stb + OFF_B + boff[p] + ksoB);
                    else      ldsm4t(bf[p], stb + OFF_B + boff[p] + ksoB);
                }
#pragma unroll
                for (int mt = 0; mt < 4; mt++)
#pragma unroll
                    for (int nt = 0; nt < 4; nt++) {
                        const int p = nt >> 1, h = (nt & 1) * 2;
                        mma16816(acc[mt][nt], ahf[mt], bf[p][h], bf[p][h + 1]);
                    }
#pragma unroll
                for (int mt = 0; mt < 4; mt++)
#pragma unroll
                    for (int nt = 0; nt < 4; nt++) {
                        const int p = nt >> 1, h = (nt & 1) * 2;
                        mma16816(acc[mt][nt], alf[mt], bf[p][h], bf[p][h + 1]);
                    }
            }
        }
        __syncthreads();
    }
#undef ISSUE

    // ------------------- epilogue -------------------
    float* Cfz = (EPI == EP_SC || EPI == EP_BIAS || EPI == EP_OUT)
                     ? Cf + (long long)z * sC : nullptr;
    __half* Chz = (EPI == EP_Q || EPI == EP_HEAD || EPI == EP_SWISH)
                      ? Ch + (long long)z * sC : nullptr;
    __half* Clz = (EPI == EP_Q || EPI == EP_HEAD || EPI == EP_SWISH)
                      ? Cl + (long long)z * sC : nullptr;

#pragma unroll
    for (int mt = 0; mt < 4; mt++) {
#pragma unroll
        for (int nt = 0; nt < 4; nt++) {
#pragma unroll
            for (int half = 0; half < 2; half++) {
                const int r = row0 + m0 + mt * 16 + (lane >> 2) + half * 8;
                const int cc = col0 + n0 + nt * 8 + (lane & 3) * 2;
                float v0 = acc[mt][nt][half * 2];
                float v1 = acc[mt][nt][half * 2 + 1];

                if (EPI == EP_SC) {
                    if (!diag || cc <= r) {
                        v0 *= 0.03125f; v1 *= 0.03125f;
                        *reinterpret_cast<float2*>(&Cfz[(long long)r * N + cc]) =
                            make_float2(v0, v1);
                    }
                } else if (EPI == EP_BIAS) {
                    float2 bb = *reinterpret_cast<const float2*>(&E[cc]);
                    *reinterpret_cast<float2*>(&Cfz[(long long)r * N + cc]) =
                        make_float2(v0 + bb.x, v1 + bb.y);
                } else if (EPI == EP_OUT) {
                    *reinterpret_cast<float2*>(&Cfz[(long long)r * N + cc]) =
                        make_float2(v0, v1);
                } else {
                    if (EPI == EP_HEAD) {
                        // residual q = qh + ql (B operand IS q in [K=S, N=D])
                        __half2 eh = *reinterpret_cast<const __half2*>(
                            &Bm[(long long)r * N + cc]);
                        __half2 el = *reinterpret_cast<const __half2*>(
                            &Bl[(long long)r * N + cc]);
                        v0 += __half2float(eh.x) + __half2float(el.x);
                        v1 += __half2float(eh.y) + __half2float(el.y);
                    }
                    if (EPI == EP_SWISH) {
                        v0 = v0 / (1.0f + expf(-v0));
                        v1 = v1 / (1.0f + expf(-v1));
                    }
                    __half h0, h1, l0, l1;
                    split_h(v0, h0, l0);
                    split_h(v1, h1, l1);
                    *reinterpret_cast<__half2*>(&Chz[(long long)r * N + cc]) =
                        __halves2half2(h0, h1);
                    *reinterpret_cast<__half2*>(&Clz[(long long)r * N + cc]) =
                        __halves2half2(l0, l1);
                }
            }
        }
    }
}

// ---------------------------------------------------------------------------
// Transpose to single fp16: dst[c][r] = fp16(src[r][c]); optional head sum
// ---------------------------------------------------------------------------
template <bool SUMH>
__global__ void tsingle(const float* __restrict__ S, __half* __restrict__ D,
                        int R, int C)
{
    __shared__ float t[32][33];
    const int tx = threadIdx.x, ty = threadIdx.y;
    const int c0 = blockIdx.x * 32, r0 = blockIdx.y * 32;
#pragma unroll
    for (int i = 0; i < 4; i++) {
        int r = r0 + ty + i * 8;
        float v;
        if (SUMH) {
            v = 0.f;
#pragma unroll
            for (int h = 0; h < 8; h++)
                v += S[(size_t)(h * 1024 + r) * C + c0 + tx];
        } else {
            v = S[(size_t)r * C + c0 + tx];
        }
        t[ty + i * 8][tx] = v;
    }
    __syncthreads();
#pragma unroll
    for (int i = 0; i < 4; i++) {
        int orow = c0 + ty + i * 8;
        D[(size_t)orow * R + r0 + tx] = __float2half(t[tx][ty + i * 8]);
    }
}

// ---------------------------------------------------------------------------
// Elementwise 2-term split (fp16)
// ---------------------------------------------------------------------------
__global__ void split_ew(const float* __restrict__ X, __half* __restrict__ H,
                         __half* __restrict__ L)
{
    size_t i = ((size_t)blockIdx.x * 256 + threadIdx.x);
    float4 v = reinterpret_cast<const float4*>(X)[i];
    __half h0, h1, h2, h3, l0, l1, l2, l3;
    split_h(v.x, h0, l0); split_h(v.y, h1, l1);
    split_h(v.z, h2, l2); split_h(v.w, h3, l3);
    reinterpret_cast<__half2*>(H)[i * 2]     = __halves2half2(h0, h1);
    reinterpret_cast<__half2*>(H)[i * 2 + 1] = __halves2half2(h2, h3);
    reinterpret_cast<__half2*>(L)[i * 2]     = __halves2half2(l0, l1);
    reinterpret_cast<__half2*>(L)[i * 2 + 1] = __halves2half2(l2, l3);
}

// ---------------------------------------------------------------------------
// Reductions
// ---------------------------------------------------------------------------
__device__ __forceinline__ float warpMax(float v) {
#pragma unroll
    for (int o = 16; o; o >>= 1) v = fmaxf(v, __shfl_xor_sync(0xffffffffu, v, o));
    return v;
}
__device__ __forceinline__ float warpSum(float v) {
#pragma unroll
    for (int o = 16; o; o >>= 1) v += __shfl_xor_sync(0xffffffffu, v, o);
    return v;
}

// Causal softmax; writes split probs only for cols < ceil((r+1)/128)*128.
__global__ __launch_bounds__(256) void softmax_split(
    const float* __restrict__ Sc, __half* __restrict__ Ph,
    __half* __restrict__ Pl)
{
    const int r = blockIdx.x & (SS - 1);
    const int kLim = ((r >> 7) + 1) << 7;
    const float* row = Sc + (long long)blockIdx.x * SS;
    __half* oh = Ph + (long long)blockIdx.x * SS;
    __half* ol = Pl + (long long)blockIdx.x * SS;
    const int tid = threadIdx.x, lane = tid & 31, w = tid >> 5;
    __shared__ float red[32];

    const int c0 = tid * 4;
    const int c1 = 1024 + tid * 4;
    float4 v0 = make_float4(NEGV, NEGV, NEGV, NEGV);
    float4 v1 = make_float4(NEGV, NEGV, NEGV, NEGV);
    if (c0 < kLim) v0 = reinterpret_cast<const float4*>(row)[tid];
    if (c1 < kLim) v1 = reinterpret_cast<const float4*>(row)[tid + 256];

    float m = -3.4e38f;
    if (c0 + 0 <= r) m = fmaxf(m, v0.x);
    if (c0 + 1 <= r) m = fmaxf(m, v0.y);
    if (c0 + 2 <= r) m = fmaxf(m, v0.z);
    if (c0 + 3 <= r) m = fmaxf(m, v0.w);
    if (c1 + 0 <= r) m = fmaxf(m, v1.x);
    if (c1 + 1 <= r) m = fmaxf(m, v1.y);
    if (c1 + 2 <= r) m = fmaxf(m, v1.z);
    if (c1 + 3 <= r) m = fmaxf(m, v1.w);
    m = warpMax(m);
    if (lane == 0) red[w] = m;
    __syncthreads();
    if (tid < 32) { float x = (tid < 8) ? red[tid] : -3.4e38f; x = warpMax(x);
                    if (tid == 0) red[0] = x; }
    __syncthreads();
    m = red[0];
    __syncthreads();

    float e[8];
    e[0] = (c0 + 0 <= r) ? expf(v0.x - m) : 0.f;
    e[1] = (c0 + 1 <= r) ? expf(v0.y - m) : 0.f;
    e[2] = (c0 + 2 <= r) ? expf(v0.z - m) : 0.f;
    e[3] = (c0 + 3 <= r) ? expf(v0.w - m) : 0.f;
    e[4] = (c1 + 0 <= r) ? expf(v1.x - m) : 0.f;
    e[5] = (c1 + 1 <= r) ? expf(v1.y - m) : 0.f;
    e[6] = (c1 + 2 <= r) ? expf(v1.z - m) : 0.f;
    e[7] = (c1 + 3 <= r) ? expf(v1.w - m) : 0.f;
    float s = e[0] + e[1] + e[2] + e[3] + e[4] + e[5] + e[6] + e[7];
    s = warpSum(s);
    if (lane == 0) red[w] = s;
    __syncthreads();
    if (tid < 32) { float x = (tid < 8) ? red[tid] : 0.f; x = warpSum(x);
                    if (tid == 0) red[0] = x; }
    __syncthreads();
    const float inv = 1.0f / red[0];

    __half h[8], l[8];
#pragma unroll
    for (int u = 0; u < 8; u++) split_h(e[u] * inv, h[u], l[u]);
    __half2* phh = reinterpret_cast<__half2*>(oh);
    __half2* pll = reinterpret_cast<__half2*>(ol);
    if (c0 < kLim) {
        phh[tid * 2]     = __halves2half2(h[0], h[1]);
        phh[tid * 2 + 1] = __halves2half2(h[2], h[3]);
        pll[tid * 2]     = __halves2half2(l[0], l[1]);
        pll[tid * 2 + 1] = __halves2half2(l[2], l[3]);
    }
    if (c1 < kLim) {
        phh[(tid + 256) * 2]     = __halves2half2(h[4], h[5]);
        phh[(tid + 256) * 2 + 1] = __halves2half2(h[6], h[7]);
        pll[(tid + 256) * 2]     = __halves2half2(l[4], l[5]);
        pll[(tid + 256) * 2 + 1] = __halves2half2(l[6], l[7]);
    }
}

// LayerNorm -> split. One block per row (1024 cols).
__global__ __launch_bounds__(256) void ln_split(
    const float* __restrict__ Hf, __half* __restrict__ Oh,
    __half* __restrict__ Ol)
{
    const float* row = Hf + (long long)blockIdx.x * DD;
    __half* oh = Oh + (long long)blockIdx.x * DD;
    __half* ol = Ol + (long long)blockIdx.x * DD;
    const int tid = threadIdx.x, lane = tid & 31, w = tid >> 5;
    __shared__ float r1[32], r2[32];

    float4 v = reinterpret_cast<const float4*>(row)[tid];
    float s = v.x + v.y + v.z + v.w;
    float s2 = v.x * v.x + v.y * v.y + v.z * v.z + v.w * v.w;
    s = warpSum(s); s2 = warpSum(s2);
    if (lane == 0) { r1[w] = s; r2[w] = s2; }
    __syncthreads();
    if (tid < 32) {
        float a = (tid < 8) ? r1[tid] : 0.f;
        float b = (tid < 8) ? r2[tid] : 0.f;
        a = warpSum(a); b = warpSum(b);
        if (tid == 0) { r1[0] = a; r2[0] = b; }
    }
    __syncthreads();
    const float mean = r1[0] * (1.0f / DD);
    const float msq = r2[0] * (1.0f / DD);
    const float inv = rsqrtf(msq - mean * mean + EPSV);

    float y[4] = {(v.x - mean) * inv, (v.y - mean) * inv,
                  (v.z - mean) * inv, (v.w - mean) * inv};
    __half h[4], l[4];
#pragma unroll
    for (int u = 0; u < 4; u++) split_h(y[u], h[u], l[u]);
    reinterpret_cast<__half2*>(oh)[tid * 2]     = __halves2half2(h[0], h[1]);
    reinterpret_cast<__half2*>(oh)[tid * 2 + 1] = __halves2half2(h[2], h[3]);
    reinterpret_cast<__half2*>(ol)[tid * 2]     = __halves2half2(l[0], l[1]);
    reinterpret_cast<__half2*>(ol)[tid * 2 + 1] = __halves2half2(l[2], l[3]);
}

// ---------------------------------------------------------------------------
// Launch
// ---------------------------------------------------------------------------
extern "C" void kernel_launch(void* const* d_in, const int* in_sizes, int n_in,
                              void* d_out, int out_size)
{
    (void)in_sizes; (void)n_in; (void)out_size;
    const float* x     = (const float*)d_in[0];
    const float* wi    = (const float*)d_in[2];
    const float* okern = (const float*)d_in[3];
    const float* obias = (const float*)d_in[4];
    float* out = (float*)d_out;

    unsigned char* base;
    cudaGetSymbolAddress((void**)&base, g_scratch);
    float* sc  = (float*)(base + O_SC);
    float* hhf = (float*)(base + O_HHF);
    __half* qh  = (__half*)(base + O_QH);
    __half* ql  = (__half*)(base + O_QL);
    __half* xh  = (__half*)(base + O_XH);
    __half* xl  = (__half*)(base + O_XL);
    __half* Pph = (__half*)(base + O_PH);
    __half* Ppl = (__half*)(base + O_PL);
    __half* hdh = (__half*)(base + O_HDH);
    __half* hdl = (__half*)(base + O_HDL);
    __half* hnh = (__half*)(base + O_HNH);
    __half* hnl = (__half*)(base + O_HNL);
    __half* fh  = (__half*)(base + O_FH);
    __half* fl  = (__half*)(base + O_FL);
    __half* wT  = (__half*)(base + O_WT);
    __half* wsT = (__half*)(base + O_WS);

    cudaFuncSetAttribute(gemm_hh<EP_Q, 0>,     cudaFuncAttributeMaxDynamicSharedMemorySize, GEMM_SMEM);
    cudaFuncSetAttribute(gemm_hh<EP_SC, 0>,    cudaFuncAttributeMaxDynamicSharedMemorySize, GEMM_SMEM);
    cudaFuncSetAttribute(gemm_hh<EP_HEAD, 1>,  cudaFuncAttributeMaxDynamicSharedMemorySize, GEMM_SMEM);
    cudaFuncSetAttribute(gemm_hh<EP_BIAS, 0>,  cudaFuncAttributeMaxDynamicSharedMemorySize, GEMM_SMEM);
    cudaFuncSetAttribute(gemm_hh<EP_SWISH, 0>, cudaFuncAttributeMaxDynamicSharedMemorySize, GEMM_SMEM);
    cudaFuncSetAttribute(gemm_hh<EP_OUT, 0>,   cudaFuncAttributeMaxDynamicSharedMemorySize, GEMM_SMEM);

    const long long sSD = (long long)SS * DD;   // 2,097,152
    const long long sSS = (long long)SS * SS;   // 4,194,304
    dim3 tb(32, 8);

    // wi^T single, Wsum^T single, x 2-term split
    tsingle<false><<<dim3(32, 32, 1), tb>>>(wi, wT, DD, DD);
    tsingle<true><<<dim3(32, 32, 1), tb>>>(okern, wsT, DD, DD);
    split_ew<<<(BSR * DD) / 1024, 256>>>(x, xh, xl);

    // q = x @ wi  (2-term split out; residual later reconstructed as qh+ql)
    gemm_hh<EP_Q, 0><<<dim3(8, 32, 1), 256, GEMM_SMEM>>>(
        xh, xl, wT, nullptr, nullptr, qh, ql, nullptr, DD, DD, 0, 0, 0, 0, 0);

    // scores = (q @ q^T)/32, lower triangle only (136 tiles per batch)
    gemm_hh<EP_SC, 0><<<dim3(136, 1, 2), 256, GEMM_SMEM>>>(
        qh, ql, qh, nullptr, sc, nullptr, nullptr, nullptr,
        DD, SS, sSD, sSD, sSS, 0, 1);

    // causal softmax -> split probs
    softmax_split<<<SB * SS, 256>>>(sc, Pph, Ppl);

    // head = q + P @ q  (trans-B: q read as [K,N]; residual from qh+ql)
    gemm_hh<EP_HEAD, 1><<<dim3(8, 16, 2), 256, GEMM_SMEM>>>(
        Pph, Ppl, qh, ql, nullptr, hdh, hdl, nullptr,
        SS, DD, sSS, sSD, sSD, sSD, 2);

    // h = head @ Wsum + bias  fp32
    gemm_hh<EP_BIAS, 0><<<dim3(8, 32, 1), 256, GEMM_SMEM>>>(
        hdh, hdl, wsT, nullptr, hhf, nullptr, nullptr, obias,
        DD, DD, 0, 0, 0, 0, 0);

    // layernorm -> split
    ln_split<<<BSR, 256>>>(hhf, hnh, hnl);

    // f = swish(h @ wi)  (split out)
    gemm_hh<EP_SWISH, 0><<<dim3(8, 32, 1), 256, GEMM_SMEM>>>(
        hnh, hnl, wT, nullptr, nullptr, fh, fl, nullptr,
        DD, DD, 0, 0, 0, 0, 0);

    // out = f @ wi  fp32
    gemm_hh<EP_OUT, 0><<<dim3(8, 32, 1), 256, GEMM_SMEM>>>(
        fh, fl, wT, nullptr, out, nullptr, nullptr, nullptr,
        DD, DD, 0, 0, 0, 0, 0);
}